// round 1
// baseline (speedup 1.0000x reference)
#include <cuda_runtime.h>
#include <math.h>

// Problem constants: B=8, C=256, H=W=256, WS=8, HEADS=4, dh=64
// HW = 65536 pixels per (b, channel) plane. 1024 windows per batch image.
#define HW 65536
#define IMW 256

// Scratch (window-major layouts):
//   g_qkv [(b*768 + o)*65536 + win*64 + t]   (1.6 GB)
//   g_attn[(b*256 + c)*65536 + win*64 + t]   (0.5 GB)
__device__ float g_qkv[402653184];
__device__ float g_attn[134217728];

// ---------------------------------------------------------------------------
// GEMM 1: qkv[o, pix] = qkv_w[o, c] @ x[c, pix] + qkv_b[o]
// N-tile = 128 tokens = 2 windows; output written in window-major scratch.
// ---------------------------------------------------------------------------
__global__ __launch_bounds__(256, 1) void qkv_gemm(const float* __restrict__ x,
                                                   const float* __restrict__ w,
                                                   const float* __restrict__ bias)
{
    __shared__ __align__(16) float As[8][128];
    __shared__ __align__(16) float Bs[8][128];

    const int tid = threadIdx.x;
    const int nt  = blockIdx.x;        // 0..511  (N tile within batch image)
    const int m0  = blockIdx.y << 7;   // 0..640
    const int b   = blockIdx.z;

    // B-tile load mapping: row c = lbk, cols lbj..lbj+3 (window-major tokens)
    const int lbk = tid >> 5;
    const int lbj = (tid & 31) << 2;
    const int win = (nt << 1) + (lbj >> 6);
    const int tt  = lbj & 63;
    const int yy  = ((win >> 5) << 3) + (tt >> 3);
    const int xx  = ((win & 31) << 3) + (tt & 7);
    const float* xp = x + ((size_t)b * 256 + lbk) * HW + yy * IMW + xx;

    // A-tile load mapping (transpose into smem)
    const int lam = tid >> 1;
    const int lak = (tid & 1) << 2;
    const float* wp = w + (size_t)(m0 + lam) * 256 + lak;

    const int r  = (tid >> 4) << 3;
    const int cc = (tid & 15) << 3;

    float acc[8][8];
#pragma unroll
    for (int i = 0; i < 8; i++)
#pragma unroll
        for (int j = 0; j < 8; j++) acc[i][j] = 0.f;

    for (int k0 = 0; k0 < 256; k0 += 8) {
        float4 av = *(const float4*)(wp + k0);
        float4 bv = *(const float4*)(xp + (size_t)k0 * HW);
        __syncthreads();
        As[lak + 0][lam] = av.x;
        As[lak + 1][lam] = av.y;
        As[lak + 2][lam] = av.z;
        As[lak + 3][lam] = av.w;
        *(float4*)&Bs[lbk][lbj] = bv;
        __syncthreads();
#pragma unroll
        for (int kk = 0; kk < 8; kk++) {
            float a[8], bb[8];
            *(float4*)&a[0]  = *(const float4*)&As[kk][r];
            *(float4*)&a[4]  = *(const float4*)&As[kk][r + 4];
            *(float4*)&bb[0] = *(const float4*)&Bs[kk][cc];
            *(float4*)&bb[4] = *(const float4*)&Bs[kk][cc + 4];
#pragma unroll
            for (int i = 0; i < 8; i++)
#pragma unroll
                for (int j = 0; j < 8; j++) acc[i][j] += a[i] * bb[j];
        }
    }

    const size_t ob = ((size_t)b * 768 + m0 + r) * HW + (size_t)nt * 128 + cc;
#pragma unroll
    for (int i = 0; i < 8; i++) {
        float bv = bias[m0 + r + i];
        float4 o0 = make_float4(acc[i][0] + bv, acc[i][1] + bv, acc[i][2] + bv, acc[i][3] + bv);
        float4 o1 = make_float4(acc[i][4] + bv, acc[i][5] + bv, acc[i][6] + bv, acc[i][7] + bv);
        *(float4*)(g_qkv + ob + (size_t)i * HW)     = o0;
        *(float4*)(g_qkv + ob + (size_t)i * HW + 4) = o1;
    }
}

// ---------------------------------------------------------------------------
// Window attention: one CTA per (window, head). 64 tokens, dh=64, fp32.
// qkv channel layout per reference: o = head*192 + {q: d, k: 64+d, v: 128+d}
// ---------------------------------------------------------------------------
__global__ __launch_bounds__(256, 1) void attn_kernel()
{
    __shared__ __align__(16) float sm[12288];   // 48 KB
    float* qs  = sm;          // [d*64 + t], 4096
    float* ks  = sm + 4096;   // [d*64 + t], 4096
    float* Ssm = sm + 8192;   // [t*64 + u], 4096
    float* Pt  = sm;          // [u*68 + t], 4348  (aliases qs + head of ks)
    float* vsT = sm + 4352;   // [u*68 + d], 4348  (aliases tail of ks + head of S)

    const int tid = threadIdx.x;
    const int wid = blockIdx.x;   // window within batch image (0..1023)
    const int hd  = blockIdx.y;   // head
    const int b   = blockIdx.z;

    const size_t qb = ((size_t)b * 768 + hd * 192) * HW + (size_t)wid * 64;
    const size_t kb = qb + (size_t)64  * HW;
    const size_t vb = qb + (size_t)128 * HW;

    float vreg[16];
#pragma unroll
    for (int n = 0; n < 16; n++) {
        int i = tid + (n << 8);
        int d = i >> 6, t = i & 63;
        qs[i]   = g_qkv[qb + (size_t)d * HW + t];
        ks[i]   = g_qkv[kb + (size_t)d * HW + t];
        vreg[n] = g_qkv[vb + (size_t)d * HW + t];
    }
    __syncthreads();

    // S[t][u] = 0.125 * sum_d q[t][d] * k[u][d]
    {
        const int rt = (tid >> 4) << 2;
        const int cu = (tid & 15) << 2;
        float sacc[4][4];
#pragma unroll
        for (int i = 0; i < 4; i++)
#pragma unroll
            for (int j = 0; j < 4; j++) sacc[i][j] = 0.f;
#pragma unroll 8
        for (int d = 0; d < 64; d++) {
            float4 a  = *(const float4*)&qs[d * 64 + rt];
            float4 bb = *(const float4*)&ks[d * 64 + cu];
            float av[4] = {a.x, a.y, a.z, a.w};
            float bv[4] = {bb.x, bb.y, bb.z, bb.w};
#pragma unroll
            for (int i = 0; i < 4; i++)
#pragma unroll
                for (int j = 0; j < 4; j++) sacc[i][j] += av[i] * bv[j];
        }
#pragma unroll
        for (int i = 0; i < 4; i++) {
            float4 sv = make_float4(sacc[i][0] * 0.125f, sacc[i][1] * 0.125f,
                                    sacc[i][2] * 0.125f, sacc[i][3] * 0.125f);
            *(float4*)&Ssm[(rt + i) * 64 + cu] = sv;
        }
    }
    __syncthreads();

    // Row softmax: warp w handles rows 8w..8w+7; results kept in registers.
    const int warp = tid >> 5, lane = tid & 31;
    float pv[16];
#pragma unroll
    for (int k = 0; k < 8; k++) {
        int rr = (warp << 3) + k;
        float s0 = Ssm[rr * 64 + lane];
        float s1 = Ssm[rr * 64 + 32 + lane];
        float m = fmaxf(s0, s1);
#pragma unroll
        for (int o = 16; o; o >>= 1) m = fmaxf(m, __shfl_xor_sync(0xffffffffu, m, o));
        float e0 = expf(s0 - m);
        float e1 = expf(s1 - m);
        float sum = e0 + e1;
#pragma unroll
        for (int o = 16; o; o >>= 1) sum += __shfl_xor_sync(0xffffffffu, sum, o);
        float inv = 1.0f / sum;
        pv[2 * k]     = e0 * inv;
        pv[2 * k + 1] = e1 * inv;
    }
    __syncthreads();   // all reads of qs/ks/S done -> safe to overwrite via aliases

#pragma unroll
    for (int k = 0; k < 8; k++) {
        int rr = (warp << 3) + k;
        Pt[lane * 68 + rr]        = pv[2 * k];
        Pt[(lane + 32) * 68 + rr] = pv[2 * k + 1];
    }
#pragma unroll
    for (int n = 0; n < 16; n++) {
        int i = tid + (n << 8);
        int d = i >> 6, t = i & 63;
        vsT[t * 68 + d] = vreg[n];
    }
    __syncthreads();

    // O[t][d] = sum_u P[t][u] v[u][d]  via outer products over u
    {
        const int rd = (tid >> 4) << 2;   // d block
        const int ct = (tid & 15) << 2;   // t block
        float oacc[4][4];
#pragma unroll
        for (int i = 0; i < 4; i++)
#pragma unroll
            for (int j = 0; j < 4; j++) oacc[i][j] = 0.f;
#pragma unroll 8
        for (int u = 0; u < 64; u++) {
            float4 a  = *(const float4*)&vsT[u * 68 + rd];
            float4 bb = *(const float4*)&Pt[u * 68 + ct];
            float av[4] = {a.x, a.y, a.z, a.w};
            float bv[4] = {bb.x, bb.y, bb.z, bb.w};
#pragma unroll
            for (int i = 0; i < 4; i++)
#pragma unroll
                for (int j = 0; j < 4; j++) oacc[i][j] += av[i] * bv[j];
        }
        const size_t ob = ((size_t)b * 256 + hd * 64 + rd) * HW + (size_t)wid * 64 + ct;
#pragma unroll
        for (int i = 0; i < 4; i++) {
            float4 ov = make_float4(oacc[i][0], oacc[i][1], oacc[i][2], oacc[i][3]);
            *(float4*)(g_attn + ob + (size_t)i * HW) = ov;
        }
    }
}

// ---------------------------------------------------------------------------
// GEMM 2: out[o, pix] = proj_w[o, c] @ attn[c, pix] + proj_b[o]
// B-source is window-major scratch (contiguous); output raster (B,C,H,W).
// ---------------------------------------------------------------------------
__global__ __launch_bounds__(256, 1) void proj_gemm(const float* __restrict__ w,
                                                    const float* __restrict__ bias,
                                                    float* __restrict__ out)
{
    __shared__ __align__(16) float As[8][128];
    __shared__ __align__(16) float Bs[8][128];

    const int tid = threadIdx.x;
    const int nt  = blockIdx.x;
    const int m0  = blockIdx.y << 7;
    const int b   = blockIdx.z;

    const int lbk = tid >> 5;
    const int lbj = (tid & 31) << 2;
    const float* ap = g_attn + ((size_t)b * 256 + lbk) * HW + (size_t)nt * 128 + lbj;

    const int lam = tid >> 1;
    const int lak = (tid & 1) << 2;
    const float* wp = w + (size_t)(m0 + lam) * 256 + lak;

    const int r  = (tid >> 4) << 3;
    const int cc = (tid & 15) << 3;

    float acc[8][8];
#pragma unroll
    for (int i = 0; i < 8; i++)
#pragma unroll
        for (int j = 0; j < 8; j++) acc[i][j] = 0.f;

    for (int k0 = 0; k0 < 256; k0 += 8) {
        float4 av = *(const float4*)(wp + k0);
        float4 bv = *(const float4*)(ap + (size_t)k0 * HW);
        __syncthreads();
        As[lak + 0][lam] = av.x;
        As[lak + 1][lam] = av.y;
        As[lak + 2][lam] = av.z;
        As[lak + 3][lam] = av.w;
        *(float4*)&Bs[lbk][lbj] = bv;
        __syncthreads();
#pragma unroll
        for (int kk = 0; kk < 8; kk++) {
            float a[8], bb[8];
            *(float4*)&a[0]  = *(const float4*)&As[kk][r];
            *(float4*)&a[4]  = *(const float4*)&As[kk][r + 4];
            *(float4*)&bb[0] = *(const float4*)&Bs[kk][cc];
            *(float4*)&bb[4] = *(const float4*)&Bs[kk][cc + 4];
#pragma unroll
            for (int i = 0; i < 8; i++)
#pragma unroll
                for (int j = 0; j < 8; j++) acc[i][j] += a[i] * bb[j];
        }
    }

    // Epilogue: scatter window-major columns back to raster layout.
    const int winc = (nt << 1) + (cc >> 6);
    const int tc   = cc & 63;                       // tc % 8 == 0
    const int yo   = ((winc >> 5) << 3) + (tc >> 3);
    const int xo   = ((winc & 31) << 3);
    float* op = out + ((size_t)b * 256 + m0 + r) * HW + yo * IMW + xo;
#pragma unroll
    for (int i = 0; i < 8; i++) {
        float bv = bias[m0 + r + i];
        float4 o0 = make_float4(acc[i][0] + bv, acc[i][1] + bv, acc[i][2] + bv, acc[i][3] + bv);
        float4 o1 = make_float4(acc[i][4] + bv, acc[i][5] + bv, acc[i][6] + bv, acc[i][7] + bv);
        *(float4*)(op + (size_t)i * HW)     = o0;
        *(float4*)(op + (size_t)i * HW + 4) = o1;
    }
}

// ---------------------------------------------------------------------------
extern "C" void kernel_launch(void* const* d_in, const int* in_sizes, int n_in,
                              void* d_out, int out_size)
{
    (void)in_sizes; (void)n_in; (void)out_size;
    const float* x      = (const float*)d_in[0];
    const float* qkv_w  = (const float*)d_in[1];
    const float* qkv_b  = (const float*)d_in[2];
    const float* proj_w = (const float*)d_in[3];
    const float* proj_b = (const float*)d_in[4];
    float* out = (float*)d_out;

    qkv_gemm<<<dim3(512, 6, 8), 256>>>(x, qkv_w, qkv_b);
    attn_kernel<<<dim3(1024, 4, 8), 256>>>();
    proj_gemm<<<dim3(512, 2, 8), 256>>>(proj_w, proj_b, out);
}

// round 3
// speedup vs baseline: 1.8386x; 1.8386x over previous
#include <cuda_runtime.h>
#include <math.h>
#include <stdint.h>

// Problem constants: B=8, C=256, H=W=256, WS=8, HEADS=4, dh=64
#define HW  65536
#define IMW 256

// Scratch (window-major token layouts):
//   g_qkv [(b*768 + o)*65536 + win*64 + t]
//   g_attn[(b*256 + c)*65536 + win*64 + t]
__device__ float g_qkv[402653184];
__device__ float g_attn[134217728];

__device__ __forceinline__ uint32_t tf32r(float f) {
    uint32_t o;
    asm("cvt.rna.tf32.f32 %0, %1;" : "=r"(o) : "f"(f));
    return o;
}

__device__ __forceinline__ void mma8(float c[4],
                                     uint32_t a0, uint32_t a1, uint32_t a2, uint32_t a3,
                                     uint32_t b0, uint32_t b1) {
    asm volatile(
        "mma.sync.aligned.m16n8k8.row.col.f32.tf32.tf32.f32 "
        "{%0,%1,%2,%3}, {%4,%5,%6,%7}, {%8,%9}, {%0,%1,%2,%3};"
        : "+f"(c[0]), "+f"(c[1]), "+f"(c[2]), "+f"(c[3])
        : "r"(a0), "r"(a1), "r"(a2), "r"(a3), "r"(b0), "r"(b1));
}

// Shared tile layout: [row][k] with 20-word row pitch (conflict-free for
// the m16n8k8 fragment pattern: bank = (20*g + t4) % 32 -> all distinct).
#define PITCH 20

// ---------------------------------------------------------------------------
// GEMM mainloop body shared by both GEMMs (macro to keep reg allocation tight)
// acc[mt][nt][4]; As/Bs are uint32 smem tiles of [128][PITCH], double buffered.
// ---------------------------------------------------------------------------
#define COMPUTE_STAGE(BUF)                                                     \
    do {                                                                       \
        _Pragma("unroll")                                                      \
        for (int ks = 0; ks < 2; ++ks) {                                       \
            const int kc0 = ks * 8 + t4;                                       \
            uint32_t af[4][4];                                                 \
            _Pragma("unroll")                                                  \
            for (int mt = 0; mt < 4; ++mt) {                                   \
                int base = (wm * 64 + mt * 16 + g) * PITCH;                    \
                af[mt][0] = As[BUF][base + kc0];                               \
                af[mt][1] = As[BUF][base + 8 * PITCH + kc0];                   \
                af[mt][2] = As[BUF][base + kc0 + 4];                           \
                af[mt][3] = As[BUF][base + 8 * PITCH + kc0 + 4];               \
            }                                                                  \
            uint32_t bf[4][2];                                                 \
            _Pragma("unroll")                                                  \
            for (int nt = 0; nt < 4; ++nt) {                                   \
                int nbase = (wn * 32 + nt * 8 + g) * PITCH;                    \
                bf[nt][0] = Bs[BUF][nbase + kc0];                              \
                bf[nt][1] = Bs[BUF][nbase + kc0 + 4];                          \
            }                                                                  \
            _Pragma("unroll")                                                  \
            for (int mt = 0; mt < 4; ++mt)                                     \
                _Pragma("unroll")                                              \
                for (int nt = 0; nt < 4; ++nt)                                 \
                    mma8(acc[mt][nt], af[mt][0], af[mt][1], af[mt][2],         \
                         af[mt][3], bf[nt][0], bf[nt][1]);                     \
        }                                                                      \
    } while (0)

// ---------------------------------------------------------------------------
// GEMM 1: qkv[o, tok] = qkv_w[o, c] @ x[c, tok] + qkv_b   (tf32 mma.sync)
// M tile 128 (out chans), N tile 128 window-major tokens (2 windows), K=256.
// ---------------------------------------------------------------------------
__global__ __launch_bounds__(256, 2) void qkv_mma(const float* __restrict__ x,
                                                  const float* __restrict__ w,
                                                  const float* __restrict__ bias)
{
    __shared__ uint32_t As[2][128 * PITCH];
    __shared__ uint32_t Bs[2][128 * PITCH];

    const int tid  = threadIdx.x;
    const int lane = tid & 31;
    const int wid  = tid >> 5;
    const int g    = lane >> 2;
    const int t4   = lane & 3;
    const int wm   = wid >> 2;
    const int wn   = wid & 3;

    const int m0 = blockIdx.x << 7;
    const int gy = blockIdx.y;
    const int b  = gy >> 9;
    const int tl = gy & 511;
    const int w0 = tl << 1;

    // load index precompute
    const int am[2]  = { tid >> 2, 64 + (tid >> 2) };
    const int akc4   = (tid & 3) << 2;
    const int bkc    = tid & 15;
    const int btok4[2] = { (tid >> 4) & 31, ((tid >> 4) + 16) & 31 };
    // B gmem pixel offsets for the two token4 chunks
    int bpix[2];
#pragma unroll
    for (int i = 0; i < 2; ++i) {
        int tok = btok4[i] << 2;
        int win = w0 + (tok >> 6);
        int t64 = tok & 63;
        bpix[i] = (((win >> 5) << 3) + (t64 >> 3)) * IMW + ((win & 31) << 3) + (t64 & 7);
    }
    const float* xb = x + (size_t)b * 256 * HW;

    float acc[4][4][4];
#pragma unroll
    for (int mt = 0; mt < 4; ++mt)
#pragma unroll
        for (int nt = 0; nt < 4; ++nt)
#pragma unroll
            for (int r = 0; r < 4; ++r) acc[mt][nt][r] = 0.f;

    float4 aR[2], bR[2];
    // prologue: stage 0
#pragma unroll
    for (int i = 0; i < 2; ++i) {
        aR[i] = *(const float4*)(w + (size_t)(m0 + am[i]) * 256 + akc4);
        bR[i] = *(const float4*)(xb + (size_t)bkc * HW + bpix[i]);
    }
#pragma unroll
    for (int i = 0; i < 2; ++i) {
        uint32_t* p = &As[0][am[i] * PITCH + akc4];
        p[0] = tf32r(aR[i].x); p[1] = tf32r(aR[i].y); p[2] = tf32r(aR[i].z); p[3] = tf32r(aR[i].w);
        uint32_t* q = &Bs[0][(btok4[i] << 2) * PITCH + bkc];
        q[0] = tf32r(bR[i].x); q[PITCH] = tf32r(bR[i].y);
        q[2 * PITCH] = tf32r(bR[i].z); q[3 * PITCH] = tf32r(bR[i].w);
    }
    __syncthreads();

    for (int s = 0; s < 16; ++s) {
        const int cb = s & 1, nb = (s + 1) & 1;
        if (s < 15) {
            const int k1 = (s + 1) << 4;
#pragma unroll
            for (int i = 0; i < 2; ++i) {
                aR[i] = *(const float4*)(w + (size_t)(m0 + am[i]) * 256 + k1 + akc4);
                bR[i] = *(const float4*)(xb + (size_t)(k1 + bkc) * HW + bpix[i]);
            }
        }
        COMPUTE_STAGE(cb);
        if (s < 15) {
#pragma unroll
            for (int i = 0; i < 2; ++i) {
                uint32_t* p = &As[nb][am[i] * PITCH + akc4];
                p[0] = tf32r(aR[i].x); p[1] = tf32r(aR[i].y); p[2] = tf32r(aR[i].z); p[3] = tf32r(aR[i].w);
                uint32_t* q = &Bs[nb][(btok4[i] << 2) * PITCH + bkc];
                q[0] = tf32r(bR[i].x); q[PITCH] = tf32r(bR[i].y);
                q[2 * PITCH] = tf32r(bR[i].z); q[3 * PITCH] = tf32r(bR[i].w);
            }
        }
        __syncthreads();
    }

    // epilogue: window-major scratch
#pragma unroll
    for (int mt = 0; mt < 4; ++mt) {
#pragma unroll
        for (int half = 0; half < 2; ++half) {
            const int o  = m0 + wm * 64 + mt * 16 + g + half * 8;
            const float bv = bias[o];
            float* drow = g_qkv + ((size_t)b * 768 + o) * HW + (size_t)tl * 128;
#pragma unroll
            for (int nt = 0; nt < 4; ++nt) {
                const int col = wn * 32 + nt * 8 + 2 * t4;
                float2 ov = make_float2(acc[mt][nt][2 * half] + bv,
                                        acc[mt][nt][2 * half + 1] + bv);
                *(float2*)(drow + col) = ov;
            }
        }
    }
}

// ---------------------------------------------------------------------------
// GEMM 2: out[o, pix] = proj_w[o, c] @ attn[c, tok] + proj_b  (tf32 mma.sync)
// ---------------------------------------------------------------------------
__global__ __launch_bounds__(256, 2) void proj_mma(const float* __restrict__ w,
                                                   const float* __restrict__ bias,
                                                   float* __restrict__ out)
{
    __shared__ uint32_t As[2][128 * PITCH];
    __shared__ uint32_t Bs[2][128 * PITCH];

    const int tid  = threadIdx.x;
    const int lane = tid & 31;
    const int wid  = tid >> 5;
    const int g    = lane >> 2;
    const int t4   = lane & 3;
    const int wm   = wid >> 2;
    const int wn   = wid & 3;

    const int m0 = blockIdx.x << 7;
    const int gy = blockIdx.y;
    const int b  = gy >> 9;
    const int tl = gy & 511;
    const int w0 = tl << 1;

    const int am[2]  = { tid >> 2, 64 + (tid >> 2) };
    const int akc4   = (tid & 3) << 2;
    const int bkc    = tid & 15;
    const int btok4[2] = { (tid >> 4) & 31, ((tid >> 4) + 16) & 31 };
    const float* ab = g_attn + (size_t)b * 256 * HW + (size_t)tl * 128;

    float acc[4][4][4];
#pragma unroll
    for (int mt = 0; mt < 4; ++mt)
#pragma unroll
        for (int nt = 0; nt < 4; ++nt)
#pragma unroll
            for (int r = 0; r < 4; ++r) acc[mt][nt][r] = 0.f;

    float4 aR[2], bR[2];
#pragma unroll
    for (int i = 0; i < 2; ++i) {
        aR[i] = *(const float4*)(w + (size_t)(m0 + am[i]) * 256 + akc4);
        bR[i] = *(const float4*)(ab + (size_t)bkc * HW + (btok4[i] << 2));
    }
#pragma unroll
    for (int i = 0; i < 2; ++i) {
        uint32_t* p = &As[0][am[i] * PITCH + akc4];
        p[0] = tf32r(aR[i].x); p[1] = tf32r(aR[i].y); p[2] = tf32r(aR[i].z); p[3] = tf32r(aR[i].w);
        uint32_t* q = &Bs[0][(btok4[i] << 2) * PITCH + bkc];
        q[0] = tf32r(bR[i].x); q[PITCH] = tf32r(bR[i].y);
        q[2 * PITCH] = tf32r(bR[i].z); q[3 * PITCH] = tf32r(bR[i].w);
    }
    __syncthreads();

    for (int s = 0; s < 16; ++s) {
        const int cb = s & 1, nb = (s + 1) & 1;
        if (s < 15) {
            const int k1 = (s + 1) << 4;
#pragma unroll
            for (int i = 0; i < 2; ++i) {
                aR[i] = *(const float4*)(w + (size_t)(m0 + am[i]) * 256 + k1 + akc4);
                bR[i] = *(const float4*)(ab + (size_t)(k1 + bkc) * HW + (btok4[i] << 2));
            }
        }
        COMPUTE_STAGE(cb);
        if (s < 15) {
#pragma unroll
            for (int i = 0; i < 2; ++i) {
                uint32_t* p = &As[nb][am[i] * PITCH + akc4];
                p[0] = tf32r(aR[i].x); p[1] = tf32r(aR[i].y); p[2] = tf32r(aR[i].z); p[3] = tf32r(aR[i].w);
                uint32_t* q = &Bs[nb][(btok4[i] << 2) * PITCH + bkc];
                q[0] = tf32r(bR[i].x); q[PITCH] = tf32r(bR[i].y);
                q[2 * PITCH] = tf32r(bR[i].z); q[3 * PITCH] = tf32r(bR[i].w);
            }
        }
        __syncthreads();
    }

    // epilogue: scatter window-major columns to raster layout
#pragma unroll
    for (int mt = 0; mt < 4; ++mt) {
#pragma unroll
        for (int half = 0; half < 2; ++half) {
            const int o  = m0 + wm * 64 + mt * 16 + g + half * 8;
            const float bv = bias[o];
            float* obase = out + ((size_t)b * 256 + o) * HW;
#pragma unroll
            for (int nt = 0; nt < 4; ++nt) {
                const int col = wn * 32 + nt * 8 + 2 * t4;
                const int win = w0 + (col >> 6);
                const int t64 = col & 63;
                const int y   = ((win >> 5) << 3) + (t64 >> 3);
                const int xx  = ((win & 31) << 3) + (t64 & 7);
                float2 ov = make_float2(acc[mt][nt][2 * half] + bv,
                                        acc[mt][nt][2 * half + 1] + bv);
                *(float2*)(obase + y * IMW + xx) = ov;
            }
        }
    }
}

// ---------------------------------------------------------------------------
// Window attention: one CTA per (window, head). 64 tokens, dh=64, fp32.
// ---------------------------------------------------------------------------
__global__ __launch_bounds__(256, 1) void attn_kernel()
{
    __shared__ __align__(16) float sm[12288];
    float* qs  = sm;
    float* ks  = sm + 4096;
    float* Ssm = sm + 8192;
    float* Pt  = sm;
    float* vsT = sm + 4352;

    const int tid = threadIdx.x;
    const int wid = blockIdx.x;
    const int hd  = blockIdx.y;
    const int b   = blockIdx.z;

    const size_t qb  = ((size_t)b * 768 + hd * 192) * HW + (size_t)wid * 64;
    const size_t kbo = qb + (size_t)64  * HW;
    const size_t vb  = qb + (size_t)128 * HW;

    float vreg[16];
#pragma unroll
    for (int n = 0; n < 16; n++) {
        int i = tid + (n << 8);
        int d = i >> 6, t = i & 63;
        qs[i]   = g_qkv[qb  + (size_t)d * HW + t];
        ks[i]   = g_qkv[kbo + (size_t)d * HW + t];
        vreg[n] = g_qkv[vb  + (size_t)d * HW + t];
    }
    __syncthreads();

    {
        const int rt = (tid >> 4) << 2;
        const int cu = (tid & 15) << 2;
        float sacc[4][4];
#pragma unroll
        for (int i = 0; i < 4; i++)
#pragma unroll
            for (int j = 0; j < 4; j++) sacc[i][j] = 0.f;
#pragma unroll 8
        for (int d = 0; d < 64; d++) {
            float4 a  = *(const float4*)&qs[d * 64 + rt];
            float4 bb = *(const float4*)&ks[d * 64 + cu];
            float av[4] = {a.x, a.y, a.z, a.w};
            float bv[4] = {bb.x, bb.y, bb.z, bb.w};
#pragma unroll
            for (int i = 0; i < 4; i++)
#pragma unroll
                for (int j = 0; j < 4; j++) sacc[i][j] += av[i] * bv[j];
        }
#pragma unroll
        for (int i = 0; i < 4; i++) {
            float4 sv = make_float4(sacc[i][0] * 0.125f, sacc[i][1] * 0.125f,
                                    sacc[i][2] * 0.125f, sacc[i][3] * 0.125f);
            *(float4*)&Ssm[(rt + i) * 64 + cu] = sv;
        }
    }
    __syncthreads();

    const int warp = tid >> 5, lane = tid & 31;
    float pv[16];
#pragma unroll
    for (int k = 0; k < 8; k++) {
        int rr = (warp << 3) + k;
        float s0 = Ssm[rr * 64 + lane];
        float s1 = Ssm[rr * 64 + 32 + lane];
        float m = fmaxf(s0, s1);
#pragma unroll
        for (int o = 16; o; o >>= 1) m = fmaxf(m, __shfl_xor_sync(0xffffffffu, m, o));
        float e0 = __expf(s0 - m);
        float e1 = __expf(s1 - m);
        float sum = e0 + e1;
#pragma unroll
        for (int o = 16; o; o >>= 1) sum += __shfl_xor_sync(0xffffffffu, sum, o);
        float inv = 1.0f / sum;
        pv[2 * k]     = e0 * inv;
        pv[2 * k + 1] = e1 * inv;
    }
    __syncthreads();

#pragma unroll
    for (int k = 0; k < 8; k++) {
        int rr = (warp << 3) + k;
        Pt[lane * 68 + rr]        = pv[2 * k];
        Pt[(lane + 32) * 68 + rr] = pv[2 * k + 1];
    }
#pragma unroll
    for (int n = 0; n < 16; n++) {
        int i = tid + (n << 8);
        int d = i >> 6, t = i & 63;
        vsT[t * 68 + d] = vreg[n];
    }
    __syncthreads();

    {
        const int rd = (tid >> 4) << 2;
        const int ct = (tid & 15) << 2;
        float oacc[4][4];
#pragma unroll
        for (int i = 0; i < 4; i++)
#pragma unroll
            for (int j = 0; j < 4; j++) oacc[i][j] = 0.f;
#pragma unroll 8
        for (int u = 0; u < 64; u++) {
            float4 a  = *(const float4*)&vsT[u * 68 + rd];
            float4 bb = *(const float4*)&Pt[u * 68 + ct];
            float av[4] = {a.x, a.y, a.z, a.w};
            float bv[4] = {bb.x, bb.y, bb.z, bb.w};
#pragma unroll
            for (int i = 0; i < 4; i++)
#pragma unroll
                for (int j = 0; j < 4; j++) oacc[i][j] += av[i] * bv[j];
        }
        const size_t ob = ((size_t)b * 256 + hd * 64 + rd) * HW + (size_t)wid * 64 + ct;
#pragma unroll
        for (int i = 0; i < 4; i++) {
            float4 ov = make_float4(oacc[i][0], oacc[i][1], oacc[i][2], oacc[i][3]);
            *(float4*)(g_attn + ob + (size_t)i * HW) = ov;
        }
    }
}

// ---------------------------------------------------------------------------
extern "C" void kernel_launch(void* const* d_in, const int* in_sizes, int n_in,
                              void* d_out, int out_size)
{
    (void)in_sizes; (void)n_in; (void)out_size;
    const float* x      = (const float*)d_in[0];
    const float* qkv_w  = (const float*)d_in[1];
    const float* qkv_b  = (const float*)d_in[2];
    const float* proj_w = (const float*)d_in[3];
    const float* proj_b = (const float*)d_in[4];
    float* out = (float*)d_out;

    qkv_mma<<<dim3(6, 4096), 256>>>(x, qkv_w, qkv_b);
    attn_kernel<<<dim3(1024, 4, 8), 256>>>();
    proj_mma<<<dim3(2, 4096), 256>>>(proj_w, proj_b, out);
}

// round 4
// speedup vs baseline: 2.5497x; 1.3868x over previous
#include <cuda_runtime.h>
#include <math.h>
#include <stdint.h>

// Problem constants: B=8, C=256, H=W=256, WS=8, HEADS=4, dh=64
#define HW  65536
#define IMW 256

// Scratch:
//  g_qkv [(b*768+o)*HW + win*64+t]    fp32 (GEMM1 out, attention in)
//  g_attn[(b*256+c)*HW + win*64+t]    tf32-rounded bits (attention out, proj B)
//  g_x   [(b*256+c)*HW + win*64+t]    tf32-rounded bits, window-major copy of x
//  g_wq [768*256], g_wp [256*256]     tf32-rounded weights
__device__ float g_qkv[402653184];
__device__ float g_attn[134217728];
__device__ float g_x[134217728];
__device__ float g_wq[196608];
__device__ float g_wp[65536];

__device__ __forceinline__ uint32_t tf32r(float f) {
    uint32_t o;
    asm("cvt.rna.tf32.f32 %0, %1;" : "=r"(o) : "f"(f));
    return o;
}
__device__ __forceinline__ float tf32rf(float f) { return __uint_as_float(tf32r(f)); }

__device__ __forceinline__ uint32_t smem_u32(const void* p) {
    uint32_t a;
    asm("{ .reg .u64 t; cvta.to.shared.u64 t, %1; cvt.u32.u64 %0, t; }" : "=r"(a) : "l"(p));
    return a;
}

__device__ __forceinline__ void mma8(float c[4],
                                     uint32_t a0, uint32_t a1, uint32_t a2, uint32_t a3,
                                     uint32_t b0, uint32_t b1) {
    asm volatile(
        "mma.sync.aligned.m16n8k8.row.col.f32.tf32.tf32.f32 "
        "{%0,%1,%2,%3}, {%4,%5,%6,%7}, {%8,%9}, {%0,%1,%2,%3};"
        : "+f"(c[0]), "+f"(c[1]), "+f"(c[2]), "+f"(c[3])
        : "r"(a0), "r"(a1), "r"(a2), "r"(a3), "r"(b0), "r"(b1));
}

#define CP16(dst, src) \
    asm volatile("cp.async.cg.shared.global [%0], [%1], 16;" :: "r"(dst), "l"(src) : "memory")
#define CP_COMMIT() asm volatile("cp.async.commit_group;" ::: "memory")
#define CP_WAIT1()  asm volatile("cp.async.wait_group 1;" ::: "memory")
#define CP_WAIT0()  asm volatile("cp.async.wait_group 0;" ::: "memory")

// smem layout (words): A[3][128*20], B[3][16*136]
#define APITCH 20
#define BPITCH 136
#define AWORDS (128 * APITCH)      // 2560
#define BWORDS (16 * BPITCH)       // 2176
#define SMEM_WORDS (3 * (AWORDS + BWORDS))
#define SMEM_BYTES (SMEM_WORDS * 4)   // 56832

// ---------------------------------------------------------------------------
// Shared GEMM machinery: CTA 128x128, 4 warps of 64x64, K stepped by 16, 16
// stages, 3-deep cp.async pipeline. A rows: [m][k] pitch 20; B: [k][tok]
// pitch 136 (both conflict-free for the m16n8k8 fragment pattern).
// ---------------------------------------------------------------------------
#define GEMM_ISSUE(S)                                                          \
    do {                                                                       \
        const int _s   = (S);                                                  \
        const int _buf = _s % 3;                                               \
        const int _k0  = _s << 4;                                              \
        const uint32_t _aB = smbase + (uint32_t)(_buf * AWORDS) * 4u;          \
        const uint32_t _bB = smbase + (uint32_t)(3 * AWORDS + _buf * BWORDS) * 4u; \
        _Pragma("unroll")                                                      \
        for (int _i = 0; _i < 4; ++_i) {                                       \
            int _m = (tid >> 2) + 32 * _i, _c = (tid & 3) << 2;                \
            CP16(_aB + (uint32_t)(_m * APITCH + _c) * 4u,                      \
                 gA + (size_t)_m * 256 + _k0 + _c);                            \
        }                                                                      \
        _Pragma("unroll")                                                      \
        for (int _i = 0; _i < 4; ++_i) {                                       \
            int _k = tid >> 3, _t = ((tid & 7) + 8 * _i) << 2;                 \
            CP16(_bB + (uint32_t)(_k * BPITCH + _t) * 4u,                      \
                 gB + (size_t)(_k0 + _k) * HW + _t);                           \
        }                                                                      \
        CP_COMMIT();                                                           \
    } while (0)

#define GEMM_COMPUTE(BUF)                                                      \
    do {                                                                       \
        const uint32_t* _A = dsm + (BUF) * AWORDS;                             \
        const uint32_t* _B = dsm + 3 * AWORDS + (BUF) * BWORDS;                \
        _Pragma("unroll")                                                      \
        for (int ks = 0; ks < 2; ++ks) {                                       \
            const int kc = ks * 8 + t4;                                        \
            uint32_t af[4][4];                                                 \
            _Pragma("unroll")                                                  \
            for (int mt = 0; mt < 4; ++mt) {                                   \
                int base = (wm * 64 + mt * 16 + g) * APITCH;                   \
                af[mt][0] = _A[base + kc];                                     \
                af[mt][1] = _A[base + 8 * APITCH + kc];                        \
                af[mt][2] = _A[base + kc + 4];                                 \
                af[mt][3] = _A[base + 8 * APITCH + kc + 4];                    \
            }                                                                  \
            uint32_t bf[8][2];                                                 \
            _Pragma("unroll")                                                  \
            for (int nt = 0; nt < 8; ++nt) {                                   \
                int tok = wn * 64 + nt * 8 + g;                                \
                bf[nt][0] = _B[kc * BPITCH + tok];                             \
                bf[nt][1] = _B[(kc + 4) * BPITCH + tok];                       \
            }                                                                  \
            _Pragma("unroll")                                                  \
            for (int mt = 0; mt < 4; ++mt)                                     \
                _Pragma("unroll")                                              \
                for (int nt = 0; nt < 8; ++nt)                                 \
                    mma8(acc[mt][nt], af[mt][0], af[mt][1], af[mt][2],         \
                         af[mt][3], bf[nt][0], bf[nt][1]);                     \
        }                                                                      \
    } while (0)

#define GEMM_PROLOG_AND_MAINLOOP()                                             \
    float acc[4][8][4];                                                        \
    _Pragma("unroll")                                                          \
    for (int mt = 0; mt < 4; ++mt)                                             \
        _Pragma("unroll")                                                      \
        for (int nt = 0; nt < 8; ++nt)                                         \
            _Pragma("unroll")                                                  \
            for (int r = 0; r < 4; ++r) acc[mt][nt][r] = 0.f;                  \
    GEMM_ISSUE(0);                                                             \
    GEMM_ISSUE(1);                                                             \
    _Pragma("unroll 1")                                                        \
    for (int s = 0; s < 16; ++s) {                                             \
        if (s < 15) { CP_WAIT1(); } else { CP_WAIT0(); }                       \
        __syncthreads();                                                       \
        if (s < 14) GEMM_ISSUE(s + 2);                                         \
        GEMM_COMPUTE(s % 3);                                                   \
    }

// ---------------------------------------------------------------------------
// GEMM 1: g_qkv[o, tok] = g_wq[o, :] @ g_x[:, tok] + qkv_b   (fp32 out)
// ---------------------------------------------------------------------------
__global__ __launch_bounds__(128) void qkv_mma(const float* __restrict__ bias)
{
    extern __shared__ uint32_t dsm[];
    const uint32_t smbase = smem_u32(dsm);

    const int tid  = threadIdx.x;
    const int lane = tid & 31;
    const int wid  = tid >> 5;
    const int g    = lane >> 2;
    const int t4   = lane & 3;
    const int wm   = wid >> 1;
    const int wn   = wid & 1;

    const int m0 = blockIdx.x << 7;      // 0..640
    const int gy = blockIdx.y;
    const int b  = gy >> 9;
    const int tl = gy & 511;

    const float* gA = g_wq + (size_t)m0 * 256;
    const float* gB = g_x + ((size_t)b * 256) * HW + (size_t)tl * 128;

    GEMM_PROLOG_AND_MAINLOOP();

#pragma unroll
    for (int mt = 0; mt < 4; ++mt) {
#pragma unroll
        for (int half = 0; half < 2; ++half) {
            const int o = m0 + wm * 64 + mt * 16 + g + half * 8;
            const float bv = bias[o];
            float* drow = g_qkv + ((size_t)b * 768 + o) * HW + (size_t)tl * 128;
#pragma unroll
            for (int nt = 0; nt < 8; ++nt) {
                const int col = wn * 64 + nt * 8 + 2 * t4;
                float2 ov = make_float2(acc[mt][nt][2 * half] + bv,
                                        acc[mt][nt][2 * half + 1] + bv);
                *(float2*)(drow + col) = ov;
            }
        }
    }
}

// ---------------------------------------------------------------------------
// GEMM 2: out[o, pix] = g_wp[o, :] @ g_attn[:, tok] + proj_b  (raster scatter)
// ---------------------------------------------------------------------------
__global__ __launch_bounds__(128) void proj_mma(const float* __restrict__ bias,
                                                float* __restrict__ out)
{
    extern __shared__ uint32_t dsm[];
    const uint32_t smbase = smem_u32(dsm);

    const int tid  = threadIdx.x;
    const int lane = tid & 31;
    const int wid  = tid >> 5;
    const int g    = lane >> 2;
    const int t4   = lane & 3;
    const int wm   = wid >> 1;
    const int wn   = wid & 1;

    const int m0 = blockIdx.x << 7;      // 0 or 128
    const int gy = blockIdx.y;
    const int b  = gy >> 9;
    const int tl = gy & 511;
    const int w0 = tl << 1;

    const float* gA = g_wp + (size_t)m0 * 256;
    const float* gB = g_attn + ((size_t)b * 256) * HW + (size_t)tl * 128;

    GEMM_PROLOG_AND_MAINLOOP();

#pragma unroll
    for (int mt = 0; mt < 4; ++mt) {
#pragma unroll
        for (int half = 0; half < 2; ++half) {
            const int o = m0 + wm * 64 + mt * 16 + g + half * 8;
            const float bv = bias[o];
            float* obase = out + ((size_t)b * 256 + o) * HW;
#pragma unroll
            for (int nt = 0; nt < 8; ++nt) {
                const int col = wn * 64 + nt * 8 + 2 * t4;
                const int win = w0 + (col >> 6);
                const int t64 = col & 63;
                const int y   = ((win >> 5) << 3) + (t64 >> 3);
                const int xx  = ((win & 31) << 3) + (t64 & 7);
                float2 ov = make_float2(acc[mt][nt][2 * half] + bv,
                                        acc[mt][nt][2 * half + 1] + bv);
                *(float2*)(obase + y * IMW + xx) = ov;
            }
        }
    }
}

// ---------------------------------------------------------------------------
// Prepass: tf32-round weights; tf32-round + window-major-transpose x.
// ---------------------------------------------------------------------------
__global__ __launch_bounds__(256) void cvt_weights(const float* __restrict__ qw,
                                                   const float* __restrict__ pw)
{
    int i = blockIdx.x * 256 + threadIdx.x;
    if (i < 196608) g_wq[i] = tf32rf(qw[i]);
    if (i < 65536)  g_wp[i] = tf32rf(pw[i]);
}

__global__ __launch_bounds__(256) void cvt_x(const float* __restrict__ x)
{
    // one float4 (4 window-major tokens) per thread
    int id    = blockIdx.x * 256 + threadIdx.x;     // 0 .. 32M-1
    int plane = id >> 14;                           // (b*256 + c)
    int rem   = id & 16383;                         // token4 within plane
    int win   = rem >> 4;
    int t64   = (rem & 15) << 2;
    int y     = ((win >> 5) << 3) + (t64 >> 3);
    int xx    = ((win & 31) << 3) + (t64 & 7);
    float4 v  = *(const float4*)(x + (size_t)plane * HW + y * IMW + xx);
    float4 o  = make_float4(tf32rf(v.x), tf32rf(v.y), tf32rf(v.z), tf32rf(v.w));
    *(float4*)(g_x + (size_t)plane * HW + (rem << 2)) = o;
}

// ---------------------------------------------------------------------------
// Window attention: one CTA per (window, head). fp32 exact; output rounded to
// tf32 so proj can cp.async it directly.
// ---------------------------------------------------------------------------
__global__ __launch_bounds__(256, 1) void attn_kernel()
{
    __shared__ __align__(16) float sm[12288];
    float* qs  = sm;
    float* ks  = sm + 4096;
    float* Ssm = sm + 8192;
    float* Pt  = sm;
    float* vsT = sm + 4352;

    const int tid = threadIdx.x;
    const int wid = blockIdx.x;
    const int hd  = blockIdx.y;
    const int b   = blockIdx.z;

    const size_t qb  = ((size_t)b * 768 + hd * 192) * HW + (size_t)wid * 64;
    const size_t kbo = qb + (size_t)64  * HW;
    const size_t vb  = qb + (size_t)128 * HW;

    float vreg[16];
#pragma unroll
    for (int n = 0; n < 16; n++) {
        int i = tid + (n << 8);
        int d = i >> 6, t = i & 63;
        qs[i]   = g_qkv[qb  + (size_t)d * HW + t];
        ks[i]   = g_qkv[kbo + (size_t)d * HW + t];
        vreg[n] = g_qkv[vb  + (size_t)d * HW + t];
    }
    __syncthreads();

    {
        const int rt = (tid >> 4) << 2;
        const int cu = (tid & 15) << 2;
        float sacc[4][4];
#pragma unroll
        for (int i = 0; i < 4; i++)
#pragma unroll
            for (int j = 0; j < 4; j++) sacc[i][j] = 0.f;
#pragma unroll 8
        for (int d = 0; d < 64; d++) {
            float4 a  = *(const float4*)&qs[d * 64 + rt];
            float4 bb = *(const float4*)&ks[d * 64 + cu];
            float av[4] = {a.x, a.y, a.z, a.w};
            float bv[4] = {bb.x, bb.y, bb.z, bb.w};
#pragma unroll
            for (int i = 0; i < 4; i++)
#pragma unroll
                for (int j = 0; j < 4; j++) sacc[i][j] += av[i] * bv[j];
        }
#pragma unroll
        for (int i = 0; i < 4; i++) {
            float4 sv = make_float4(sacc[i][0] * 0.125f, sacc[i][1] * 0.125f,
                                    sacc[i][2] * 0.125f, sacc[i][3] * 0.125f);
            *(float4*)&Ssm[(rt + i) * 64 + cu] = sv;
        }
    }
    __syncthreads();

    const int warp = tid >> 5, lane = tid & 31;
    float pv[16];
#pragma unroll
    for (int k = 0; k < 8; k++) {
        int rr = (warp << 3) + k;
        float s0 = Ssm[rr * 64 + lane];
        float s1 = Ssm[rr * 64 + 32 + lane];
        float m = fmaxf(s0, s1);
#pragma unroll
        for (int o = 16; o; o >>= 1) m = fmaxf(m, __shfl_xor_sync(0xffffffffu, m, o));
        float e0 = __expf(s0 - m);
        float e1 = __expf(s1 - m);
        float sum = e0 + e1;
#pragma unroll
        for (int o = 16; o; o >>= 1) sum += __shfl_xor_sync(0xffffffffu, sum, o);
        float inv = 1.0f / sum;
        pv[2 * k]     = e0 * inv;
        pv[2 * k + 1] = e1 * inv;
    }
    __syncthreads();

#pragma unroll
    for (int k = 0; k < 8; k++) {
        int rr = (warp << 3) + k;
        Pt[lane * 68 + rr]        = pv[2 * k];
        Pt[(lane + 32) * 68 + rr] = pv[2 * k + 1];
    }
#pragma unroll
    for (int n = 0; n < 16; n++) {
        int i = tid + (n << 8);
        int d = i >> 6, t = i & 63;
        vsT[t * 68 + d] = vreg[n];
    }
    __syncthreads();

    {
        const int rd = (tid >> 4) << 2;
        const int ct = (tid & 15) << 2;
        float oacc[4][4];
#pragma unroll
        for (int i = 0; i < 4; i++)
#pragma unroll
            for (int j = 0; j < 4; j++) oacc[i][j] = 0.f;
#pragma unroll 8
        for (int u = 0; u < 64; u++) {
            float4 a  = *(const float4*)&vsT[u * 68 + rd];
            float4 bb = *(const float4*)&Pt[u * 68 + ct];
            float av[4] = {a.x, a.y, a.z, a.w};
            float bv[4] = {bb.x, bb.y, bb.z, bb.w};
#pragma unroll
            for (int i = 0; i < 4; i++)
#pragma unroll
                for (int j = 0; j < 4; j++) oacc[i][j] += av[i] * bv[j];
        }
        const size_t ob = ((size_t)b * 256 + hd * 64 + rd) * HW + (size_t)wid * 64 + ct;
#pragma unroll
        for (int i = 0; i < 4; i++) {
            float4 ov = make_float4(tf32rf(oacc[i][0]), tf32rf(oacc[i][1]),
                                    tf32rf(oacc[i][2]), tf32rf(oacc[i][3]));
            *(float4*)(g_attn + ob + (size_t)i * HW) = ov;
        }
    }
}

// ---------------------------------------------------------------------------
extern "C" void kernel_launch(void* const* d_in, const int* in_sizes, int n_in,
                              void* d_out, int out_size)
{
    (void)in_sizes; (void)n_in; (void)out_size;
    const float* x      = (const float*)d_in[0];
    const float* qkv_w  = (const float*)d_in[1];
    const float* qkv_b  = (const float*)d_in[2];
    const float* proj_w = (const float*)d_in[3];
    const float* proj_b = (const float*)d_in[4];
    float* out = (float*)d_out;

    static int attr_done = 0;
    if (!attr_done) {
        cudaFuncSetAttribute(qkv_mma,  cudaFuncAttributeMaxDynamicSharedMemorySize, SMEM_BYTES);
        cudaFuncSetAttribute(proj_mma, cudaFuncAttributeMaxDynamicSharedMemorySize, SMEM_BYTES);
        attr_done = 1;
    }

    cvt_weights<<<768, 256>>>(qkv_w, proj_w);
    cvt_x<<<131072, 256>>>(x);
    qkv_mma<<<dim3(6, 4096), 128, SMEM_BYTES>>>(qkv_b);
    attn_kernel<<<dim3(1024, 4, 8), 256>>>();
    proj_mma<<<dim3(2, 4096), 128, SMEM_BYTES>>>(proj_b, out);
}

// round 5
// speedup vs baseline: 3.1970x; 1.2538x over previous
#include <cuda_runtime.h>
#include <math.h>
#include <stdint.h>

// Problem constants: B=8, C=256, H=W=256, WS=8, HEADS=4, dh=64
#define HW  65536
#define IMW 256

// Scratch:
//  g_qkv [(b*768+o)*HW + win*64+t]    fp32 (GEMM1 out, attention in)
//  g_attn[(b*256+c)*HW + win*64+t]    tf32-rounded bits (attention out, proj B)
//  g_x   [(b*256+c)*HW + win*64+t]    tf32-rounded bits, window-major copy of x
//  g_wq [768*256], g_wp [256*256]     tf32-rounded weights
__device__ float g_qkv[402653184];
__device__ float g_attn[134217728];
__device__ float g_x[134217728];
__device__ float g_wq[196608];
__device__ float g_wp[65536];

__device__ __forceinline__ uint32_t tf32r(float f) {
    uint32_t o;
    asm("cvt.rna.tf32.f32 %0, %1;" : "=r"(o) : "f"(f));
    return o;
}
__device__ __forceinline__ float tf32rf(float f) { return __uint_as_float(tf32r(f)); }

__device__ __forceinline__ uint32_t smem_u32(const void* p) {
    uint32_t a;
    asm("{ .reg .u64 t; cvta.to.shared.u64 t, %1; cvt.u32.u64 %0, t; }" : "=r"(a) : "l"(p));
    return a;
}

__device__ __forceinline__ void mma8(float c[4],
                                     uint32_t a0, uint32_t a1, uint32_t a2, uint32_t a3,
                                     uint32_t b0, uint32_t b1) {
    asm volatile(
        "mma.sync.aligned.m16n8k8.row.col.f32.tf32.tf32.f32 "
        "{%0,%1,%2,%3}, {%4,%5,%6,%7}, {%8,%9}, {%0,%1,%2,%3};"
        : "+f"(c[0]), "+f"(c[1]), "+f"(c[2]), "+f"(c[3])
        : "r"(a0), "r"(a1), "r"(a2), "r"(a3), "r"(b0), "r"(b1));
}

#define CP16(dst, src) \
    asm volatile("cp.async.cg.shared.global [%0], [%1], 16;" :: "r"(dst), "l"(src) : "memory")
#define CP_COMMIT() asm volatile("cp.async.commit_group;" ::: "memory")
#define CP_WAIT1()  asm volatile("cp.async.wait_group 1;" ::: "memory")
#define CP_WAIT0()  asm volatile("cp.async.wait_group 0;" ::: "memory")

// GEMM smem layout (words): A[3][128*20], B[3][16*136]
#define APITCH 20
#define BPITCH 136
#define AWORDS (128 * APITCH)
#define BWORDS (16 * BPITCH)
#define SMEM_WORDS (3 * (AWORDS + BWORDS))
#define SMEM_BYTES (SMEM_WORDS * 4)   // 56832

// Attention smem: 3 buffers of [64][68] words
#define TPITCH 68
#define TWORDS (64 * TPITCH)                 // 4352
#define ATTN_SMEM_BYTES (3 * TWORDS * 4)     // 52224

// ---------------------------------------------------------------------------
// Shared GEMM machinery: CTA 128x128, 4 warps of 64x64, K stepped by 16,
// 16 stages, 3-deep cp.async pipeline.
// ---------------------------------------------------------------------------
#define GEMM_ISSUE(S)                                                          \
    do {                                                                       \
        const int _s   = (S);                                                  \
        const int _buf = _s % 3;                                               \
        const int _k0  = _s << 4;                                              \
        const uint32_t _aB = smbase + (uint32_t)(_buf * AWORDS) * 4u;          \
        const uint32_t _bB = smbase + (uint32_t)(3 * AWORDS + _buf * BWORDS) * 4u; \
        _Pragma("unroll")                                                      \
        for (int _i = 0; _i < 4; ++_i) {                                       \
            int _m = (tid >> 2) + 32 * _i, _c = (tid & 3) << 2;                \
            CP16(_aB + (uint32_t)(_m * APITCH + _c) * 4u,                      \
                 gA + (size_t)_m * 256 + _k0 + _c);                            \
        }                                                                      \
        _Pragma("unroll")                                                      \
        for (int _i = 0; _i < 4; ++_i) {                                       \
            int _k = tid >> 3, _t = ((tid & 7) + 8 * _i) << 2;                 \
            CP16(_bB + (uint32_t)(_k * BPITCH + _t) * 4u,                      \
                 gB + (size_t)(_k0 + _k) * HW + _t);                           \
        }                                                                      \
        CP_COMMIT();                                                           \
    } while (0)

#define GEMM_COMPUTE(BUF)                                                      \
    do {                                                                       \
        const uint32_t* _A = dsm + (BUF) * AWORDS;                             \
        const uint32_t* _B = dsm + 3 * AWORDS + (BUF) * BWORDS;                \
        _Pragma("unroll")                                                      \
        for (int ks = 0; ks < 2; ++ks) {                                       \
            const int kc = ks * 8 + t4;                                        \
            uint32_t af[4][4];                                                 \
            _Pragma("unroll")                                                  \
            for (int mt = 0; mt < 4; ++mt) {                                   \
                int base = (wm * 64 + mt * 16 + g) * APITCH;                   \
                af[mt][0] = _A[base + kc];                                     \
                af[mt][1] = _A[base + 8 * APITCH + kc];                        \
                af[mt][2] = _A[base + kc + 4];                                 \
                af[mt][3] = _A[base + 8 * APITCH + kc + 4];                    \
            }                                                                  \
            uint32_t bf[8][2];                                                 \
            _Pragma("unroll")                                                  \
            for (int nt = 0; nt < 8; ++nt) {                                   \
                int tok = wn * 64 + nt * 8 + g;                                \
                bf[nt][0] = _B[kc * BPITCH + tok];                             \
                bf[nt][1] = _B[(kc + 4) * BPITCH + tok];                       \
            }                                                                  \
            _Pragma("unroll")                                                  \
            for (int mt = 0; mt < 4; ++mt)                                     \
                _Pragma("unroll")                                              \
                for (int nt = 0; nt < 8; ++nt)                                 \
                    mma8(acc[mt][nt], af[mt][0], af[mt][1], af[mt][2],         \
                         af[mt][3], bf[nt][0], bf[nt][1]);                     \
        }                                                                      \
    } while (0)

#define GEMM_PROLOG_AND_MAINLOOP()                                             \
    float acc[4][8][4];                                                        \
    _Pragma("unroll")                                                          \
    for (int mt = 0; mt < 4; ++mt)                                             \
        _Pragma("unroll")                                                      \
        for (int nt = 0; nt < 8; ++nt)                                         \
            _Pragma("unroll")                                                  \
            for (int r = 0; r < 4; ++r) acc[mt][nt][r] = 0.f;                  \
    GEMM_ISSUE(0);                                                             \
    GEMM_ISSUE(1);                                                             \
    _Pragma("unroll 1")                                                        \
    for (int s = 0; s < 16; ++s) {                                             \
        if (s < 15) { CP_WAIT1(); } else { CP_WAIT0(); }                       \
        __syncthreads();                                                       \
        if (s < 14) GEMM_ISSUE(s + 2);                                         \
        GEMM_COMPUTE(s % 3);                                                   \
    }

// ---------------------------------------------------------------------------
// GEMM 1: g_qkv[o, tok] = g_wq[o, :] @ g_x[:, tok] + qkv_b   (fp32 out)
// ---------------------------------------------------------------------------
__global__ __launch_bounds__(128) void qkv_mma(const float* __restrict__ bias)
{
    extern __shared__ uint32_t dsm[];
    const uint32_t smbase = smem_u32(dsm);

    const int tid  = threadIdx.x;
    const int lane = tid & 31;
    const int wid  = tid >> 5;
    const int g    = lane >> 2;
    const int t4   = lane & 3;
    const int wm   = wid >> 1;
    const int wn   = wid & 1;

    const int m0 = blockIdx.x << 7;
    const int gy = blockIdx.y;
    const int b  = gy >> 9;
    const int tl = gy & 511;

    const float* gA = g_wq + (size_t)m0 * 256;
    const float* gB = g_x + ((size_t)b * 256) * HW + (size_t)tl * 128;

    GEMM_PROLOG_AND_MAINLOOP();

#pragma unroll
    for (int mt = 0; mt < 4; ++mt) {
#pragma unroll
        for (int half = 0; half < 2; ++half) {
            const int o = m0 + wm * 64 + mt * 16 + g + half * 8;
            const float bv = bias[o];
            float* drow = g_qkv + ((size_t)b * 768 + o) * HW + (size_t)tl * 128;
#pragma unroll
            for (int nt = 0; nt < 8; ++nt) {
                const int col = wn * 64 + nt * 8 + 2 * t4;
                float2 ov = make_float2(acc[mt][nt][2 * half] + bv,
                                        acc[mt][nt][2 * half + 1] + bv);
                *(float2*)(drow + col) = ov;
            }
        }
    }
}

// ---------------------------------------------------------------------------
// GEMM 2: out[o, pix] = g_wp[o, :] @ g_attn[:, tok] + proj_b  (raster scatter)
// ---------------------------------------------------------------------------
__global__ __launch_bounds__(128) void proj_mma(const float* __restrict__ bias,
                                                float* __restrict__ out)
{
    extern __shared__ uint32_t dsm[];
    const uint32_t smbase = smem_u32(dsm);

    const int tid  = threadIdx.x;
    const int lane = tid & 31;
    const int wid  = tid >> 5;
    const int g    = lane >> 2;
    const int t4   = lane & 3;
    const int wm   = wid >> 1;
    const int wn   = wid & 1;

    const int m0 = blockIdx.x << 7;
    const int gy = blockIdx.y;
    const int b  = gy >> 9;
    const int tl = gy & 511;
    const int w0 = tl << 1;

    const float* gA = g_wp + (size_t)m0 * 256;
    const float* gB = g_attn + ((size_t)b * 256) * HW + (size_t)tl * 128;

    GEMM_PROLOG_AND_MAINLOOP();

#pragma unroll
    for (int mt = 0; mt < 4; ++mt) {
#pragma unroll
        for (int half = 0; half < 2; ++half) {
            const int o = m0 + wm * 64 + mt * 16 + g + half * 8;
            const float bv = bias[o];
            float* obase = out + ((size_t)b * 256 + o) * HW;
#pragma unroll
            for (int nt = 0; nt < 8; ++nt) {
                const int col = wn * 64 + nt * 8 + 2 * t4;
                const int win = w0 + (col >> 6);
                const int t64 = col & 63;
                const int y   = ((win >> 5) << 3) + (t64 >> 3);
                const int xx  = ((win & 31) << 3) + (t64 & 7);
                float2 ov = make_float2(acc[mt][nt][2 * half] + bv,
                                        acc[mt][nt][2 * half + 1] + bv);
                *(float2*)(obase + y * IMW + xx) = ov;
            }
        }
    }
}

// ---------------------------------------------------------------------------
// Prepass: tf32-round weights; tf32-round + window-major-transpose x.
// ---------------------------------------------------------------------------
__global__ __launch_bounds__(256) void cvt_weights(const float* __restrict__ qw,
                                                   const float* __restrict__ pw)
{
    int i = blockIdx.x * 256 + threadIdx.x;
    if (i < 196608) g_wq[i] = tf32rf(qw[i]);
    if (i < 65536)  g_wp[i] = tf32rf(pw[i]);
}

__global__ __launch_bounds__(256) void cvt_x(const float* __restrict__ x)
{
    int id    = blockIdx.x * 256 + threadIdx.x;
    int plane = id >> 14;
    int rem   = id & 16383;
    int win   = rem >> 4;
    int t64   = (rem & 15) << 2;
    int y     = ((win >> 5) << 3) + (t64 >> 3);
    int xx    = ((win & 31) << 3) + (t64 & 7);
    float4 v  = *(const float4*)(x + (size_t)plane * HW + y * IMW + xx);
    float4 o  = make_float4(tf32rf(v.x), tf32rf(v.y), tf32rf(v.z), tf32rf(v.w));
    *(float4*)(g_x + (size_t)plane * HW + (rem << 2)) = o;
}

// ---------------------------------------------------------------------------
// Tensor-core window attention: one CTA (4 warps) per (window, head).
// q_s/k_s token-major [t][d] pitch 68; v_s d-major [d][u] pitch 68.
// p_s aliases q_s; o_s aliases k_s. Deferred softmax normalization.
// ---------------------------------------------------------------------------
__global__ __launch_bounds__(128) void attn_mma()
{
    extern __shared__ float smf[];
    float* q_s = smf;                 // [64][68]  -> later P
    float* k_s = smf + TWORDS;        // [64][68]  -> later O^T
    float* v_s = smf + 2 * TWORDS;    // [64][68]

    const int tid  = threadIdx.x;
    const int lane = tid & 31;
    const int wrp  = tid >> 5;
    const int g    = lane >> 2;
    const int t4   = lane & 3;
    const int r0   = wrp * 16 + g;    // first owned S row

    const int win = blockIdx.x;
    const int hd  = blockIdx.y;
    const int b   = blockIdx.z;

    const float* gq = g_qkv + ((size_t)b * 768 + hd * 192) * HW + (size_t)win * 64;
    const float* gk = gq + (size_t)64  * HW;
    const float* gv = gq + (size_t)128 * HW;

    // Stage q (pre-scaled by exact 0.125), k transposed to [t][d]; v direct [d][u].
#pragma unroll
    for (int i = 0; i < 8; ++i) {
        int idx = tid + i * 128;
        int d = idx >> 4, c4 = (idx & 15) << 2;
        float4 qv = *(const float4*)(gq + (size_t)d * HW + c4);
        q_s[(c4 + 0) * TPITCH + d] = tf32rf(0.125f * qv.x);
        q_s[(c4 + 1) * TPITCH + d] = tf32rf(0.125f * qv.y);
        q_s[(c4 + 2) * TPITCH + d] = tf32rf(0.125f * qv.z);
        q_s[(c4 + 3) * TPITCH + d] = tf32rf(0.125f * qv.w);
        float4 kv = *(const float4*)(gk + (size_t)d * HW + c4);
        k_s[(c4 + 0) * TPITCH + d] = tf32rf(kv.x);
        k_s[(c4 + 1) * TPITCH + d] = tf32rf(kv.y);
        k_s[(c4 + 2) * TPITCH + d] = tf32rf(kv.z);
        k_s[(c4 + 3) * TPITCH + d] = tf32rf(kv.w);
        float4 vv = *(const float4*)(gv + (size_t)d * HW + c4);
        float4 vr = make_float4(tf32rf(vv.x), tf32rf(vv.y), tf32rf(vv.z), tf32rf(vv.w));
        *(float4*)&v_s[d * TPITCH + c4] = vr;
    }
    __syncthreads();

    const uint32_t* qsu = (const uint32_t*)q_s;
    const uint32_t* ksu = (const uint32_t*)k_s;
    const uint32_t* vsu = (const uint32_t*)v_s;

    // S = (0.125 q)^T k : warp owns rows r0..r0+15 (as 16-row fragment)
    float acc[8][4];
#pragma unroll
    for (int nt = 0; nt < 8; ++nt)
#pragma unroll
        for (int r = 0; r < 4; ++r) acc[nt][r] = 0.f;

#pragma unroll
    for (int ks = 0; ks < 8; ++ks) {
        const int kc = t4 + 8 * ks;
        uint32_t a0 = qsu[r0 * TPITCH + kc];
        uint32_t a1 = qsu[(r0 + 8) * TPITCH + kc];
        uint32_t a2 = qsu[r0 * TPITCH + kc + 4];
        uint32_t a3 = qsu[(r0 + 8) * TPITCH + kc + 4];
#pragma unroll
        for (int nt = 0; nt < 8; ++nt) {
            uint32_t b0 = ksu[(g + 8 * nt) * TPITCH + kc];
            uint32_t b1 = ksu[(g + 8 * nt) * TPITCH + kc + 4];
            mma8(acc[nt], a0, a1, a2, a3, b0, b1);
        }
    }

    // Softmax over rows r0 and r0+8 (quad-distributed): unnormalized exp.
    float mx0 = -1e30f, mx1 = -1e30f;
#pragma unroll
    for (int nt = 0; nt < 8; ++nt) {
        mx0 = fmaxf(mx0, fmaxf(acc[nt][0], acc[nt][1]));
        mx1 = fmaxf(mx1, fmaxf(acc[nt][2], acc[nt][3]));
    }
    mx0 = fmaxf(mx0, __shfl_xor_sync(0xffffffffu, mx0, 1));
    mx0 = fmaxf(mx0, __shfl_xor_sync(0xffffffffu, mx0, 2));
    mx1 = fmaxf(mx1, __shfl_xor_sync(0xffffffffu, mx1, 1));
    mx1 = fmaxf(mx1, __shfl_xor_sync(0xffffffffu, mx1, 2));

    float sm0 = 0.f, sm1 = 0.f;
#pragma unroll
    for (int nt = 0; nt < 8; ++nt) {
        acc[nt][0] = __expf(acc[nt][0] - mx0);
        acc[nt][1] = __expf(acc[nt][1] - mx0);
        acc[nt][2] = __expf(acc[nt][2] - mx1);
        acc[nt][3] = __expf(acc[nt][3] - mx1);
        sm0 += acc[nt][0] + acc[nt][1];
        sm1 += acc[nt][2] + acc[nt][3];
    }
    sm0 += __shfl_xor_sync(0xffffffffu, sm0, 1);
    sm0 += __shfl_xor_sync(0xffffffffu, sm0, 2);
    sm1 += __shfl_xor_sync(0xffffffffu, sm1, 1);
    sm1 += __shfl_xor_sync(0xffffffffu, sm1, 2);
    const float inv0 = 1.0f / sm0;
    const float inv1 = 1.0f / sm1;

    // Write unnormalized P (tf32) into p_s = q_s (warp-local region only).
    __syncwarp();
    float* p_s = q_s;
#pragma unroll
    for (int nt = 0; nt < 8; ++nt) {
        const int c = 8 * nt + 2 * t4;
        p_s[r0 * TPITCH + c]           = tf32rf(acc[nt][0]);
        p_s[r0 * TPITCH + c + 1]       = tf32rf(acc[nt][1]);
        p_s[(r0 + 8) * TPITCH + c]     = tf32rf(acc[nt][2]);
        p_s[(r0 + 8) * TPITCH + c + 1] = tf32rf(acc[nt][3]);
    }
    __syncwarp();

    // O' = P' v  (rows r0..r0+15, cols d 0..63)
    float oac[8][4];
#pragma unroll
    for (int nt = 0; nt < 8; ++nt)
#pragma unroll
        for (int r = 0; r < 4; ++r) oac[nt][r] = 0.f;

#pragma unroll
    for (int ks = 0; ks < 8; ++ks) {
        const int kc = t4 + 8 * ks;
        uint32_t a0 = qsu[r0 * TPITCH + kc];
        uint32_t a1 = qsu[(r0 + 8) * TPITCH + kc];
        uint32_t a2 = qsu[r0 * TPITCH + kc + 4];
        uint32_t a3 = qsu[(r0 + 8) * TPITCH + kc + 4];
#pragma unroll
        for (int nt = 0; nt < 8; ++nt) {
            uint32_t b0 = vsu[(g + 8 * nt) * TPITCH + kc];
            uint32_t b1 = vsu[(g + 8 * nt) * TPITCH + kc + 4];
            mma8(oac[nt], a0, a1, a2, a3, b0, b1);
        }
    }

    // Transpose O through o_s = k_s (all k_s reads done after this barrier).
    __syncthreads();
    float* o_s = k_s;
#pragma unroll
    for (int nt = 0; nt < 8; ++nt) {
        const int c = 8 * nt + 2 * t4;
        o_s[c * TPITCH + r0]           = oac[nt][0] * inv0;
        o_s[(c + 1) * TPITCH + r0]     = oac[nt][1] * inv0;
        o_s[c * TPITCH + r0 + 8]       = oac[nt][2] * inv1;
        o_s[(c + 1) * TPITCH + r0 + 8] = oac[nt][3] * inv1;
    }
    __syncthreads();

    // Coalesced d-major write, rounded to tf32 for proj's cp.async path.
    float* ga = g_attn + ((size_t)b * 256 + hd * 64) * HW + (size_t)win * 64;
#pragma unroll
    for (int i = 0; i < 8; ++i) {
        int idx = tid + i * 128;
        int d = idx >> 4, c4 = (idx & 15) << 2;
        float4 ov = *(const float4*)&o_s[d * TPITCH + c4];
        float4 orr = make_float4(tf32rf(ov.x), tf32rf(ov.y), tf32rf(ov.z), tf32rf(ov.w));
        *(float4*)(ga + (size_t)d * HW + c4) = orr;
    }
}

// ---------------------------------------------------------------------------
extern "C" void kernel_launch(void* const* d_in, const int* in_sizes, int n_in,
                              void* d_out, int out_size)
{
    (void)in_sizes; (void)n_in; (void)out_size;
    const float* x      = (const float*)d_in[0];
    const float* qkv_w  = (const float*)d_in[1];
    const float* qkv_b  = (const float*)d_in[2];
    const float* proj_w = (const float*)d_in[3];
    const float* proj_b = (const float*)d_in[4];
    float* out = (float*)d_out;

    static int attr_done = 0;
    if (!attr_done) {
        cudaFuncSetAttribute(qkv_mma,  cudaFuncAttributeMaxDynamicSharedMemorySize, SMEM_BYTES);
        cudaFuncSetAttribute(proj_mma, cudaFuncAttributeMaxDynamicSharedMemorySize, SMEM_BYTES);
        cudaFuncSetAttribute(attn_mma, cudaFuncAttributeMaxDynamicSharedMemorySize, ATTN_SMEM_BYTES);
        attr_done = 1;
    }

    cvt_weights<<<768, 256>>>(qkv_w, proj_w);
    cvt_x<<<131072, 256>>>(x);
    qkv_mma<<<dim3(6, 4096), 128, SMEM_BYTES>>>(qkv_b);
    attn_mma<<<dim3(1024, 4, 8), 128, ATTN_SMEM_BYTES>>>();
    proj_mma<<<dim3(2, 4096), 128, SMEM_BYTES>>>(proj_b, out);
}

// round 6
// speedup vs baseline: 3.5781x; 1.1192x over previous
#include <cuda_runtime.h>
#include <math.h>
#include <stdint.h>

// Problem constants: B=8, C=256, H=W=256, WS=8, HEADS=4, dh=64
#define HW  65536
#define IMW 256

// Scratch:
//  g_qkv [(b*768+o)*HW + win*64+t]  fp32 (GEMM1 out, attention in)
//  g_attn B-fragment-packed tf32: [b][t8 8192][kt 32][64]   (attn out, proj B)
//  g_x    B-fragment-packed tf32: [b][t8 8192][kt 32][64]   (qkv B)
//  g_wq/g_wp A-fragment-packed tf32: [mt][kt 32][128]
// Fragment word indices (m16n8k8 tf32):
//  A tile (16m x 8k):  widx = ((m%8)*4 + (k%4))*4 + ((m%16)>>3) + 2*((k%8)>>2)
//  B tile (8k x 8n):   widx = ((n%8)*4 + (k%4))*2 + ((k%8)>>2)
__device__ float g_qkv[402653184];
__device__ float g_attn[134217728];
__device__ float g_x[134217728];
__device__ float g_wq[196608];
__device__ float g_wp[65536];

__device__ __forceinline__ uint32_t tf32r(float f) {
    uint32_t o;
    asm("cvt.rna.tf32.f32 %0, %1;" : "=r"(o) : "f"(f));
    return o;
}
__device__ __forceinline__ float tf32rf(float f) { return __uint_as_float(tf32r(f)); }

__device__ __forceinline__ uint32_t smem_u32(const void* p) {
    uint32_t a;
    asm("{ .reg .u64 t; cvta.to.shared.u64 t, %1; cvt.u32.u64 %0, t; }" : "=r"(a) : "l"(p));
    return a;
}

__device__ __forceinline__ void mma8(float c[4],
                                     uint32_t a0, uint32_t a1, uint32_t a2, uint32_t a3,
                                     uint32_t b0, uint32_t b1) {
    asm volatile(
        "mma.sync.aligned.m16n8k8.row.col.f32.tf32.tf32.f32 "
        "{%0,%1,%2,%3}, {%4,%5,%6,%7}, {%8,%9}, {%0,%1,%2,%3};"
        : "+f"(c[0]), "+f"(c[1]), "+f"(c[2]), "+f"(c[3])
        : "r"(a0), "r"(a1), "r"(a2), "r"(a3), "r"(b0), "r"(b1));
}

#define CP16(dst, src) \
    asm volatile("cp.async.cg.shared.global [%0], [%1], 16;" :: "r"(dst), "l"(src) : "memory")
#define CP_COMMIT() asm volatile("cp.async.commit_group;" ::: "memory")
#define CP_WAIT1()  asm volatile("cp.async.wait_group 1;" ::: "memory")
#define CP_WAIT0()  asm volatile("cp.async.wait_group 0;" ::: "memory")

// GEMM smem: A stage = 8 mtiles x 2 ktiles x 128 words = 2048; B stage =
// 16 t8tiles x 2 ktiles x 64 words = 2048. 3 stages each -> 49152 bytes.
#define AWORDS 2048
#define BWORDS 2048
#define SMEM_BYTES (3 * (AWORDS + BWORDS) * 4)

// Attention smem: 3 buffers of [64][68] words
#define TPITCH 68
#define TWORDS (64 * TPITCH)
#define ATTN_SMEM_BYTES (3 * TWORDS * 4)

// ---------------------------------------------------------------------------
// Shared GEMM machinery: CTA 128x128, 4 warps of 64x64, K stepped by 16,
// 16 stages, 3-deep cp.async pipeline, fragment-packed operands.
//  gA: A-packed base for this CTA's 8 mtiles (mt stride 4096 words)
//  gB: B-packed base for this CTA's 16 t8tiles (t8 stride 2048 words)
// ---------------------------------------------------------------------------
#define GEMM_ISSUE(S)                                                          \
    do {                                                                       \
        const int _s   = (S);                                                  \
        const int _buf = _s % 3;                                               \
        const uint32_t _aB = smbase + (uint32_t)(_buf * AWORDS) * 4u;          \
        const uint32_t _bB = smbase + (uint32_t)((3 * AWORDS + _buf * BWORDS)) * 4u; \
        _Pragma("unroll")                                                      \
        for (int _i = 0; _i < 4; ++_i) {                                       \
            int _c = tid + (_i << 7);                                          \
            CP16(_aB + (uint32_t)_c * 16u,                                     \
                 gA + ((size_t)(_c >> 6) * 4096 + _s * 256 + (_c & 63) * 4));  \
            CP16(_bB + (uint32_t)_c * 16u,                                     \
                 gB + ((size_t)(_c >> 5) * 2048 + _s * 128 + (_c & 31) * 4));  \
        }                                                                      \
        CP_COMMIT();                                                           \
    } while (0)

#define GEMM_COMPUTE(BUF)                                                      \
    do {                                                                       \
        const uint32_t* _A = dsm + (BUF) * AWORDS;                             \
        const uint32_t* _B = dsm + 3 * AWORDS + (BUF) * BWORDS;                \
        _Pragma("unroll")                                                      \
        for (int ks = 0; ks < 2; ++ks) {                                       \
            uint4 af[4];                                                       \
            _Pragma("unroll")                                                  \
            for (int mt = 0; mt < 4; ++mt)                                     \
                af[mt] = *(const uint4*)(_A + (((wm * 4 + mt) * 2 + ks) << 7)  \
                                              + (lane << 2));                  \
            uint2 bf[8];                                                       \
            _Pragma("unroll")                                                  \
            for (int nt = 0; nt < 8; ++nt)                                     \
                bf[nt] = *(const uint2*)(_B + (((wn * 8 + nt)) << 7)           \
                                              + (ks << 6) + (lane << 1));      \
            _Pragma("unroll")                                                  \
            for (int mt = 0; mt < 4; ++mt)                                     \
                _Pragma("unroll")                                              \
                for (int nt = 0; nt < 8; ++nt)                                 \
                    mma8(acc[mt][nt], af[mt].x, af[mt].y, af[mt].z, af[mt].w,  \
                         bf[nt].x, bf[nt].y);                                  \
        }                                                                      \
    } while (0)

#define GEMM_PROLOG_AND_MAINLOOP()                                             \
    float acc[4][8][4];                                                        \
    _Pragma("unroll")                                                          \
    for (int mt = 0; mt < 4; ++mt)                                             \
        _Pragma("unroll")                                                      \
        for (int nt = 0; nt < 8; ++nt)                                         \
            _Pragma("unroll")                                                  \
            for (int r = 0; r < 4; ++r) acc[mt][nt][r] = 0.f;                  \
    GEMM_ISSUE(0);                                                             \
    GEMM_ISSUE(1);                                                             \
    _Pragma("unroll 1")                                                        \
    for (int s = 0; s < 16; ++s) {                                             \
        if (s < 15) { CP_WAIT1(); } else { CP_WAIT0(); }                       \
        __syncthreads();                                                       \
        if (s < 14) GEMM_ISSUE(s + 2);                                         \
        GEMM_COMPUTE(s % 3);                                                   \
    }

// ---------------------------------------------------------------------------
// GEMM 1: g_qkv[o, tok] = qkv_w @ x + qkv_b   (fp32 out, window-major tokens)
// ---------------------------------------------------------------------------
__global__ __launch_bounds__(128) void qkv_mma(const float* __restrict__ bias)
{
    extern __shared__ uint32_t dsm[];
    const uint32_t smbase = smem_u32(dsm);

    const int tid  = threadIdx.x;
    const int lane = tid & 31;
    const int wid  = tid >> 5;
    const int g    = lane >> 2;
    const int t4   = lane & 3;
    const int wm   = wid >> 1;
    const int wn   = wid & 1;

    const int m0 = blockIdx.x << 7;
    const int gy = blockIdx.y;
    const int b  = gy >> 9;
    const int tl = gy & 511;

    const float* gA = g_wq + (size_t)(m0 >> 4) * 4096;
    const float* gB = g_x + (size_t)b * 16777216 + (size_t)tl * 16 * 2048;

    GEMM_PROLOG_AND_MAINLOOP();

#pragma unroll
    for (int mt = 0; mt < 4; ++mt) {
#pragma unroll
        for (int half = 0; half < 2; ++half) {
            const int o = m0 + wm * 64 + mt * 16 + g + half * 8;
            const float bv = bias[o];
            float* drow = g_qkv + ((size_t)b * 768 + o) * HW + (size_t)tl * 128;
#pragma unroll
            for (int nt = 0; nt < 8; ++nt) {
                const int col = wn * 64 + nt * 8 + 2 * t4;
                float2 ov = make_float2(acc[mt][nt][2 * half] + bv,
                                        acc[mt][nt][2 * half + 1] + bv);
                *(float2*)(drow + col) = ov;
            }
        }
    }
}

// ---------------------------------------------------------------------------
// GEMM 2: out[o, pix] = proj_w @ attn + proj_b  (raster scatter epilogue)
// ---------------------------------------------------------------------------
__global__ __launch_bounds__(128) void proj_mma(const float* __restrict__ bias,
                                                float* __restrict__ out)
{
    extern __shared__ uint32_t dsm[];
    const uint32_t smbase = smem_u32(dsm);

    const int tid  = threadIdx.x;
    const int lane = tid & 31;
    const int wid  = tid >> 5;
    const int g    = lane >> 2;
    const int t4   = lane & 3;
    const int wm   = wid >> 1;
    const int wn   = wid & 1;

    const int m0 = blockIdx.x << 7;
    const int gy = blockIdx.y;
    const int b  = gy >> 9;
    const int tl = gy & 511;
    const int w0 = tl << 1;

    const float* gA = g_wp + (size_t)(m0 >> 4) * 4096;
    const float* gB = g_attn + (size_t)b * 16777216 + (size_t)tl * 16 * 2048;

    GEMM_PROLOG_AND_MAINLOOP();

#pragma unroll
    for (int mt = 0; mt < 4; ++mt) {
#pragma unroll
        for (int half = 0; half < 2; ++half) {
            const int o = m0 + wm * 64 + mt * 16 + g + half * 8;
            const float bv = bias[o];
            float* obase = out + ((size_t)b * 256 + o) * HW;
#pragma unroll
            for (int nt = 0; nt < 8; ++nt) {
                const int col = wn * 64 + nt * 8 + 2 * t4;
                const int win = w0 + (col >> 6);
                const int t64 = col & 63;
                const int y   = ((win >> 5) << 3) + (t64 >> 3);
                const int xx  = ((win & 31) << 3) + (t64 & 7);
                float2 ov = make_float2(acc[mt][nt][2 * half] + bv,
                                        acc[mt][nt][2 * half + 1] + bv);
                *(float2*)(obase + y * IMW + xx) = ov;
            }
        }
    }
}

// ---------------------------------------------------------------------------
// Prepass: tf32-round weights into A-fragment-packed layout.
// ---------------------------------------------------------------------------
__global__ __launch_bounds__(256) void cvt_weights(const float* __restrict__ qw,
                                                   const float* __restrict__ pw)
{
    int i = blockIdx.x * 256 + threadIdx.x;
    if (i < 196608) {
        int o = i >> 8, c = i & 255;
        int widx = ((o & 7) * 4 + (c & 3)) * 4 + ((o >> 3) & 1) + 2 * ((c >> 2) & 1);
        g_wq[(((o >> 4) * 32) + (c >> 3)) * 128 + widx] = tf32rf(qw[i]);
    }
    if (i < 65536) {
        int o = i >> 8, c = i & 255;
        int widx = ((o & 7) * 4 + (c & 3)) * 4 + ((o >> 3) & 1) + 2 * ((c >> 2) & 1);
        g_wp[(((o >> 4) * 32) + (c >> 3)) * 128 + widx] = tf32rf(pw[i]);
    }
}

// ---------------------------------------------------------------------------
// Prepass: tf32-round + window-major + B-fragment-pack x.
// One thread per fragment pair (channels c, c+4 at one token).
// ---------------------------------------------------------------------------
__global__ __launch_bounds__(256) void cvt_x(const float* __restrict__ x)
{
    int id  = blockIdx.x * 256 + threadIdx.x;    // 0 .. 2^26-1
    int t4  = id & 3;
    int g   = (id >> 2) & 7;
    int kt  = (id >> 5) & 31;
    int t8  = (id >> 10) & 8191;
    int b   = id >> 23;

    int c0  = kt * 8 + t4;
    int tok = t8 * 8 + g;
    int win = tok >> 6, t64 = tok & 63;
    int y   = ((win >> 5) << 3) + (t64 >> 3);
    int xx  = ((win & 31) << 3) + (t64 & 7);

    float v0 = x[((size_t)(b * 256 + c0)) * HW + y * IMW + xx];
    float v1 = x[((size_t)(b * 256 + c0 + 4)) * HW + y * IMW + xx];
    size_t wa = (size_t)b * 16777216 + ((size_t)(t8 * 32 + kt)) * 64 + (g * 4 + t4) * 2;
    float2 o = make_float2(tf32rf(v0), tf32rf(v1));
    *(float2*)(g_x + wa) = o;
}

// ---------------------------------------------------------------------------
// Tensor-core window attention: one CTA (4 warps) per (window, head).
// Epilogue writes g_attn in B-fragment-packed layout.
// ---------------------------------------------------------------------------
__global__ __launch_bounds__(128) void attn_mma()
{
    extern __shared__ float smf[];
    float* q_s = smf;                 // [64][68]  -> later P
    float* k_s = smf + TWORDS;        // [64][68]  -> later O^T ([d][t])
    float* v_s = smf + 2 * TWORDS;    // [64][68]

    const int tid  = threadIdx.x;
    const int lane = tid & 31;
    const int wrp  = tid >> 5;
    const int g    = lane >> 2;
    const int t4   = lane & 3;
    const int r0   = wrp * 16 + g;

    const int win = blockIdx.x;
    const int hd  = blockIdx.y;
    const int b   = blockIdx.z;

    const float* gq = g_qkv + ((size_t)b * 768 + hd * 192) * HW + (size_t)win * 64;
    const float* gk = gq + (size_t)64  * HW;
    const float* gv = gq + (size_t)128 * HW;

#pragma unroll
    for (int i = 0; i < 8; ++i) {
        int idx = tid + i * 128;
        int d = idx >> 4, c4 = (idx & 15) << 2;
        float4 qv = *(const float4*)(gq + (size_t)d * HW + c4);
        q_s[(c4 + 0) * TPITCH + d] = tf32rf(0.125f * qv.x);
        q_s[(c4 + 1) * TPITCH + d] = tf32rf(0.125f * qv.y);
        q_s[(c4 + 2) * TPITCH + d] = tf32rf(0.125f * qv.z);
        q_s[(c4 + 3) * TPITCH + d] = tf32rf(0.125f * qv.w);
        float4 kv = *(const float4*)(gk + (size_t)d * HW + c4);
        k_s[(c4 + 0) * TPITCH + d] = tf32rf(kv.x);
        k_s[(c4 + 1) * TPITCH + d] = tf32rf(kv.y);
        k_s[(c4 + 2) * TPITCH + d] = tf32rf(kv.z);
        k_s[(c4 + 3) * TPITCH + d] = tf32rf(kv.w);
        float4 vv = *(const float4*)(gv + (size_t)d * HW + c4);
        float4 vr = make_float4(tf32rf(vv.x), tf32rf(vv.y), tf32rf(vv.z), tf32rf(vv.w));
        *(float4*)&v_s[d * TPITCH + c4] = vr;
    }
    __syncthreads();

    const uint32_t* qsu = (const uint32_t*)q_s;
    const uint32_t* ksu = (const uint32_t*)k_s;
    const uint32_t* vsu = (const uint32_t*)v_s;

    float acc[8][4];
#pragma unroll
    for (int nt = 0; nt < 8; ++nt)
#pragma unroll
        for (int r = 0; r < 4; ++r) acc[nt][r] = 0.f;

#pragma unroll
    for (int ks = 0; ks < 8; ++ks) {
        const int kc = t4 + 8 * ks;
        uint32_t a0 = qsu[r0 * TPITCH + kc];
        uint32_t a1 = qsu[(r0 + 8) * TPITCH + kc];
        uint32_t a2 = qsu[r0 * TPITCH + kc + 4];
        uint32_t a3 = qsu[(r0 + 8) * TPITCH + kc + 4];
#pragma unroll
        for (int nt = 0; nt < 8; ++nt) {
            uint32_t b0 = ksu[(g + 8 * nt) * TPITCH + kc];
            uint32_t b1 = ksu[(g + 8 * nt) * TPITCH + kc + 4];
            mma8(acc[nt], a0, a1, a2, a3, b0, b1);
        }
    }

    float mx0 = -1e30f, mx1 = -1e30f;
#pragma unroll
    for (int nt = 0; nt < 8; ++nt) {
        mx0 = fmaxf(mx0, fmaxf(acc[nt][0], acc[nt][1]));
        mx1 = fmaxf(mx1, fmaxf(acc[nt][2], acc[nt][3]));
    }
    mx0 = fmaxf(mx0, __shfl_xor_sync(0xffffffffu, mx0, 1));
    mx0 = fmaxf(mx0, __shfl_xor_sync(0xffffffffu, mx0, 2));
    mx1 = fmaxf(mx1, __shfl_xor_sync(0xffffffffu, mx1, 1));
    mx1 = fmaxf(mx1, __shfl_xor_sync(0xffffffffu, mx1, 2));

    float sm0 = 0.f, sm1 = 0.f;
#pragma unroll
    for (int nt = 0; nt < 8; ++nt) {
        acc[nt][0] = __expf(acc[nt][0] - mx0);
        acc[nt][1] = __expf(acc[nt][1] - mx0);
        acc[nt][2] = __expf(acc[nt][2] - mx1);
        acc[nt][3] = __expf(acc[nt][3] - mx1);
        sm0 += acc[nt][0] + acc[nt][1];
        sm1 += acc[nt][2] + acc[nt][3];
    }
    sm0 += __shfl_xor_sync(0xffffffffu, sm0, 1);
    sm0 += __shfl_xor_sync(0xffffffffu, sm0, 2);
    sm1 += __shfl_xor_sync(0xffffffffu, sm1, 1);
    sm1 += __shfl_xor_sync(0xffffffffu, sm1, 2);
    const float inv0 = 1.0f / sm0;
    const float inv1 = 1.0f / sm1;

    __syncwarp();
    float* p_s = q_s;
#pragma unroll
    for (int nt = 0; nt < 8; ++nt) {
        const int c = 8 * nt + 2 * t4;
        p_s[r0 * TPITCH + c]           = tf32rf(acc[nt][0]);
        p_s[r0 * TPITCH + c + 1]       = tf32rf(acc[nt][1]);
        p_s[(r0 + 8) * TPITCH + c]     = tf32rf(acc[nt][2]);
        p_s[(r0 + 8) * TPITCH + c + 1] = tf32rf(acc[nt][3]);
    }
    __syncwarp();

    float oac[8][4];
#pragma unroll
    for (int nt = 0; nt < 8; ++nt)
#pragma unroll
        for (int r = 0; r < 4; ++r) oac[nt][r] = 0.f;

#pragma unroll
    for (int ks = 0; ks < 8; ++ks) {
        const int kc = t4 + 8 * ks;
        uint32_t a0 = qsu[r0 * TPITCH + kc];
        uint32_t a1 = qsu[(r0 + 8) * TPITCH + kc];
        uint32_t a2 = qsu[r0 * TPITCH + kc + 4];
        uint32_t a3 = qsu[(r0 + 8) * TPITCH + kc + 4];
#pragma unroll
        for (int nt = 0; nt < 8; ++nt) {
            uint32_t b0 = vsu[(g + 8 * nt) * TPITCH + kc];
            uint32_t b1 = vsu[(g + 8 * nt) * TPITCH + kc + 4];
            mma8(oac[nt], a0, a1, a2, a3, b0, b1);
        }
    }

    // Transpose normalized O into o_s = k_s as [d][t].
    __syncthreads();
    float* o_s = k_s;
#pragma unroll
    for (int nt = 0; nt < 8; ++nt) {
        const int c = 8 * nt + 2 * t4;
        o_s[c * TPITCH + r0]           = oac[nt][0] * inv0;
        o_s[(c + 1) * TPITCH + r0]     = oac[nt][1] * inv0;
        o_s[c * TPITCH + r0 + 8]       = oac[nt][2] * inv1;
        o_s[(c + 1) * TPITCH + r0 + 8] = oac[nt][3] * inv1;
    }
    __syncthreads();

    // B-fragment-packed store to g_attn (tf32-rounded).
    float* ga = g_attn + (size_t)b * 16777216;
#pragma unroll
    for (int i = 0; i < 16; ++i) {
        int p    = tid + i * 128;          // 0..2047
        int pt4  = p & 3;
        int pg   = (p >> 2) & 7;
        int ktL  = (p >> 5) & 7;
        int t8L  = (p >> 8) & 7;
        int d0   = ktL * 8 + pt4;
        int t    = t8L * 8 + pg;
        float v0 = o_s[d0 * TPITCH + t];
        float v1 = o_s[(d0 + 4) * TPITCH + t];
        size_t wa = ((size_t)((win * 8 + t8L) * 32 + hd * 8 + ktL)) * 64
                    + (pg * 4 + pt4) * 2;
        float2 ov = make_float2(tf32rf(v0), tf32rf(v1));
        *(float2*)(ga + wa) = ov;
    }
}

// ---------------------------------------------------------------------------
extern "C" void kernel_launch(void* const* d_in, const int* in_sizes, int n_in,
                              void* d_out, int out_size)
{
    (void)in_sizes; (void)n_in; (void)out_size;
    const float* x      = (const float*)d_in[0];
    const float* qkv_w  = (const float*)d_in[1];
    const float* qkv_b  = (const float*)d_in[2];
    const float* proj_w = (const float*)d_in[3];
    const float* proj_b = (const float*)d_in[4];
    float* out = (float*)d_out;

    static int attr_done = 0;
    if (!attr_done) {
        cudaFuncSetAttribute(qkv_mma,  cudaFuncAttributeMaxDynamicSharedMemorySize, SMEM_BYTES);
        cudaFuncSetAttribute(proj_mma, cudaFuncAttributeMaxDynamicSharedMemorySize, SMEM_BYTES);
        cudaFuncSetAttribute(attn_mma, cudaFuncAttributeMaxDynamicSharedMemorySize, ATTN_SMEM_BYTES);
        attr_done = 1;
    }

    cvt_weights<<<768, 256>>>(qkv_w, proj_w);
    cvt_x<<<262144, 256>>>(x);
    qkv_mma<<<dim3(6, 4096), 128, SMEM_BYTES>>>(qkv_b);
    attn_mma<<<dim3(1024, 4, 8), 128, ATTN_SMEM_BYTES>>>();
    proj_mma<<<dim3(2, 4096), 128, SMEM_BYTES>>>(proj_b, out);
}

// round 7
// speedup vs baseline: 3.8150x; 1.0662x over previous
#include <cuda_runtime.h>
#include <math.h>
#include <stdint.h>

// Problem constants: B=8, C=256, H=W=256, WS=8, HEADS=4, dh=64
#define HW  65536
#define IMW 256

// Scratch:
//  g_qkv: three 134217728-word regions, all tf32-rounded, fragment-packed:
//   Q (A-frag):  [b][hd][win][tt4][kt8][128]; widx=4*((t%8)*4+(d%3..)) see code
//   K (B-frag paired): [b][hd][win][tok8 8][kt2 4][128]
//   V (B-frag paired): [b][hd][win][dt 8][ut2 4][128]
//  g_attn/g_x: pair-packed B-frags for the GEMMs: [b][t8 8192][kt2 16][128]
//   word = 4*((t%8)*4 + (c&3)) + 2*((c>>3)&1) + ((c>>2)&1)
//  g_wq/g_wp: A-frag packed [mt][kt 32][128]
__device__ float g_qkv[402653184];
__device__ float g_attn[134217728];
__device__ float g_x[134217728];
__device__ float g_wq[196608];
__device__ float g_wp[65536];

#define KOFF 134217728
#define VOFF 268435456

__device__ __forceinline__ uint32_t tf32r(float f) {
    uint32_t o;
    asm("cvt.rna.tf32.f32 %0, %1;" : "=r"(o) : "f"(f));
    return o;
}
__device__ __forceinline__ float tf32rf(float f) { return __uint_as_float(tf32r(f)); }

__device__ __forceinline__ uint32_t smem_u32(const void* p) {
    uint32_t a;
    asm("{ .reg .u64 t; cvta.to.shared.u64 t, %1; cvt.u32.u64 %0, t; }" : "=r"(a) : "l"(p));
    return a;
}

__device__ __forceinline__ void mma8(float c[4],
                                     uint32_t a0, uint32_t a1, uint32_t a2, uint32_t a3,
                                     uint32_t b0, uint32_t b1) {
    asm volatile(
        "mma.sync.aligned.m16n8k8.row.col.f32.tf32.tf32.f32 "
        "{%0,%1,%2,%3}, {%4,%5,%6,%7}, {%8,%9}, {%0,%1,%2,%3};"
        : "+f"(c[0]), "+f"(c[1]), "+f"(c[2]), "+f"(c[3])
        : "r"(a0), "r"(a1), "r"(a2), "r"(a3), "r"(b0), "r"(b1));
}

#define CP16(dst, src) \
    asm volatile("cp.async.cg.shared.global [%0], [%1], 16;" :: "r"(dst), "l"(src) : "memory")
#define CP_COMMIT() asm volatile("cp.async.commit_group;" ::: "memory")
#define CP_WAIT1()  asm volatile("cp.async.wait_group 1;" ::: "memory")
#define CP_WAIT0()  asm volatile("cp.async.wait_group 0;" ::: "memory")

#define AWORDS 2048
#define BWORDS 2048
#define SMEM_BYTES (3 * (AWORDS + BWORDS) * 4)   // 49152
#define ATTN_SMEM_BYTES 32768

// ---------------------------------------------------------------------------
// Shared GEMM machinery: CTA 128x128, 4 warps of 64x64, K stepped by 16,
// 16 stages, 3-deep cp.async pipeline, fragment-packed operands.
// ---------------------------------------------------------------------------
#define GEMM_ISSUE(S)                                                          \
    do {                                                                       \
        const int _s   = (S);                                                  \
        const int _buf = _s % 3;                                               \
        const uint32_t _aB = smbase + (uint32_t)(_buf * AWORDS) * 4u;          \
        const uint32_t _bB = smbase + (uint32_t)((3 * AWORDS + _buf * BWORDS)) * 4u; \
        _Pragma("unroll")                                                      \
        for (int _i = 0; _i < 4; ++_i) {                                       \
            int _c = tid + (_i << 7);                                          \
            CP16(_aB + (uint32_t)_c * 16u,                                     \
                 gA + ((size_t)(_c >> 6) * 4096 + _s * 256 + (_c & 63) * 4));  \
            CP16(_bB + (uint32_t)_c * 16u,                                     \
                 gB + ((size_t)(_c >> 5) * 2048 + _s * 128 + (_c & 31) * 4));  \
        }                                                                      \
        CP_COMMIT();                                                           \
    } while (0)

#define GEMM_COMPUTE(BUF)                                                      \
    do {                                                                       \
        const uint32_t* _A = dsm + (BUF) * AWORDS;                             \
        const uint32_t* _B = dsm + 3 * AWORDS + (BUF) * BWORDS;                \
        uint4 bf[8];                                                           \
        _Pragma("unroll")                                                      \
        for (int nt = 0; nt < 8; ++nt)                                         \
            bf[nt] = *(const uint4*)(_B + ((wn * 8 + nt) << 7) + (lane << 2)); \
        _Pragma("unroll")                                                      \
        for (int ks = 0; ks < 2; ++ks) {                                       \
            uint4 af[4];                                                       \
            _Pragma("unroll")                                                  \
            for (int mt = 0; mt < 4; ++mt)                                     \
                af[mt] = *(const uint4*)(_A + (((wm * 4 + mt) * 2 + ks) << 7)  \
                                              + (lane << 2));                  \
            _Pragma("unroll")                                                  \
            for (int mt = 0; mt < 4; ++mt)                                     \
                _Pragma("unroll")                                              \
                for (int nt = 0; nt < 8; ++nt)                                 \
                    mma8(acc[mt][nt], af[mt].x, af[mt].y, af[mt].z, af[mt].w,  \
                         ks ? bf[nt].z : bf[nt].x, ks ? bf[nt].w : bf[nt].y);  \
        }                                                                      \
    } while (0)

#define GEMM_PROLOG_AND_MAINLOOP()                                             \
    float acc[4][8][4];                                                        \
    _Pragma("unroll")                                                          \
    for (int mt = 0; mt < 4; ++mt)                                             \
        _Pragma("unroll")                                                      \
        for (int nt = 0; nt < 8; ++nt)                                         \
            _Pragma("unroll")                                                  \
            for (int r = 0; r < 4; ++r) acc[mt][nt][r] = 0.f;                  \
    GEMM_ISSUE(0);                                                             \
    GEMM_ISSUE(1);                                                             \
    _Pragma("unroll 1")                                                        \
    for (int s = 0; s < 16; ++s) {                                             \
        if (s < 15) { CP_WAIT1(); } else { CP_WAIT0(); }                       \
        __syncthreads();                                                       \
        if (s < 14) GEMM_ISSUE(s + 2);                                         \
        GEMM_COMPUTE(s % 3);                                                   \
    }

// ---------------------------------------------------------------------------
// GEMM 1: qkv = qkv_w @ x + qkv_b; epilogue writes fragment-packed Q/K/V.
// ---------------------------------------------------------------------------
__global__ __launch_bounds__(128) void qkv_mma(const float* __restrict__ bias)
{
    extern __shared__ uint32_t dsm[];
    const uint32_t smbase = smem_u32(dsm);

    const int tid  = threadIdx.x;
    const int lane = tid & 31;
    const int wid  = tid >> 5;
    const int g    = lane >> 2;
    const int t4   = lane & 3;
    const int wm   = wid >> 1;
    const int wn   = wid & 1;

    const int m0 = blockIdx.x << 7;
    const int gy = blockIdx.y;
    const int b  = gy >> 9;
    const int tl = gy & 511;
    const int w0 = tl << 1;

    const float* gA = g_wq + (size_t)(m0 >> 4) * 4096;
    const float* gB = g_x + (size_t)b * 16777216 + (size_t)tl * 16 * 2048;

    GEMM_PROLOG_AND_MAINLOOP();

    // Epilogue: one 64-channel group per warp -> uniform type (q/k/v).
    const int g64  = 2 * blockIdx.x + wm;
    const int head = g64 / 3;
    const int typ  = g64 % 3;
    const size_t ubase = ((size_t)(b * 4 + head) * 1024 + w0 + wn) * 4096;
    const int ga3 = g & 3, gh = (g >> 2) & 1;

    if (typ == 0) {
        float* gout = g_qkv + ubase;
#pragma unroll
        for (int mt = 0; mt < 4; ++mt)
#pragma unroll
            for (int half = 0; half < 2; ++half) {
                const float bv = bias[g64 * 64 + mt * 16 + 8 * half + g];
                const int kt = mt * 2 + half;
#pragma unroll
                for (int nt = 0; nt < 8; ++nt)
#pragma unroll
                    for (int e = 0; e < 2; ++e) {
                        int d23 = 2 * t4 + e;
                        int adr = (nt >> 1) * 1024 + kt * 128
                                  + 4 * (d23 * 4 + ga3) + (nt & 1) + 2 * gh;
                        gout[adr] = tf32rf(0.125f * (acc[mt][nt][2 * half + e] + bv));
                    }
            }
    } else if (typ == 1) {
        float* gout = g_qkv + KOFF + ubase;
#pragma unroll
        for (int mt = 0; mt < 4; ++mt)
#pragma unroll
            for (int half = 0; half < 2; ++half) {
                const float bv = bias[g64 * 64 + mt * 16 + 8 * half + g];
#pragma unroll
                for (int nt = 0; nt < 8; ++nt)
#pragma unroll
                    for (int e = 0; e < 2; ++e) {
                        int d23 = 2 * t4 + e;
                        int adr = (nt * 4 + mt) * 128
                                  + 4 * (d23 * 4 + ga3) + 2 * half + gh;
                        gout[adr] = tf32rf(acc[mt][nt][2 * half + e] + bv);
                    }
            }
    } else {
        float* gout = g_qkv + VOFF + ubase;
#pragma unroll
        for (int mt = 0; mt < 4; ++mt)
#pragma unroll
            for (int half = 0; half < 2; ++half) {
                const float bv = bias[g64 * 64 + mt * 16 + 8 * half + g];
                const int dt = mt * 2 + half;
#pragma unroll
                for (int nt = 0; nt < 8; ++nt)
#pragma unroll
                    for (int e = 0; e < 2; ++e) {
                        int d23 = 2 * t4 + e;
                        int adr = (dt * 4 + (nt >> 1)) * 128
                                  + 4 * (g * 4 + (d23 & 3)) + 2 * (nt & 1) + (d23 >> 2);
                        gout[adr] = tf32rf(acc[mt][nt][2 * half + e] + bv);
                    }
            }
    }
}

// ---------------------------------------------------------------------------
// GEMM 2: out = proj_w @ attn + proj_b  (raster scatter epilogue)
// ---------------------------------------------------------------------------
__global__ __launch_bounds__(128) void proj_mma(const float* __restrict__ bias,
                                                float* __restrict__ out)
{
    extern __shared__ uint32_t dsm[];
    const uint32_t smbase = smem_u32(dsm);

    const int tid  = threadIdx.x;
    const int lane = tid & 31;
    const int wid  = tid >> 5;
    const int g    = lane >> 2;
    const int t4   = lane & 3;
    const int wm   = wid >> 1;
    const int wn   = wid & 1;

    const int m0 = blockIdx.x << 7;
    const int gy = blockIdx.y;
    const int b  = gy >> 9;
    const int tl = gy & 511;
    const int w0 = tl << 1;

    const float* gA = g_wp + (size_t)(m0 >> 4) * 4096;
    const float* gB = g_attn + (size_t)b * 16777216 + (size_t)tl * 16 * 2048;

    GEMM_PROLOG_AND_MAINLOOP();

#pragma unroll
    for (int mt = 0; mt < 4; ++mt) {
#pragma unroll
        for (int half = 0; half < 2; ++half) {
            const int o = m0 + wm * 64 + mt * 16 + g + half * 8;
            const float bv = bias[o];
            float* obase = out + ((size_t)b * 256 + o) * HW;
#pragma unroll
            for (int nt = 0; nt < 8; ++nt) {
                const int col = wn * 64 + nt * 8 + 2 * t4;
                const int win = w0 + (col >> 6);
                const int t64 = col & 63;
                const int y   = ((win >> 5) << 3) + (t64 >> 3);
                const int xx  = ((win & 31) << 3) + (t64 & 7);
                float2 ov = make_float2(acc[mt][nt][2 * half] + bv,
                                        acc[mt][nt][2 * half + 1] + bv);
                *(float2*)(obase + y * IMW + xx) = ov;
            }
        }
    }
}

// ---------------------------------------------------------------------------
// Prepass: tf32-round weights into A-fragment-packed layout.
// ---------------------------------------------------------------------------
__global__ __launch_bounds__(256) void cvt_weights(const float* __restrict__ qw,
                                                   const float* __restrict__ pw)
{
    int i = blockIdx.x * 256 + threadIdx.x;
    if (i < 196608) {
        int o = i >> 8, c = i & 255;
        int widx = ((o & 7) * 4 + (c & 3)) * 4 + ((o >> 3) & 1) + 2 * ((c >> 2) & 1);
        g_wq[(((o >> 4) * 32) + (c >> 3)) * 128 + widx] = tf32rf(qw[i]);
    }
    if (i < 65536) {
        int o = i >> 8, c = i & 255;
        int widx = ((o & 7) * 4 + (c & 3)) * 4 + ((o >> 3) & 1) + 2 * ((c >> 2) & 1);
        g_wp[(((o >> 4) * 32) + (c >> 3)) * 128 + widx] = tf32rf(pw[i]);
    }
}

// ---------------------------------------------------------------------------
// Prepass: tf32-round + window-major + pair-packed B-fragment x.
// ---------------------------------------------------------------------------
__global__ __launch_bounds__(256) void cvt_x(const float* __restrict__ x)
{
    int id  = blockIdx.x * 256 + threadIdx.x;    // 0 .. 2^26-1
    int t4  = id & 3;
    int g   = (id >> 2) & 7;
    int kt  = (id >> 5) & 31;
    int t8  = (id >> 10) & 8191;
    int b   = id >> 23;

    int c0  = kt * 8 + t4;
    int tok = t8 * 8 + g;
    int win = tok >> 6, t64 = tok & 63;
    int y   = ((win >> 5) << 3) + (t64 >> 3);
    int xx  = ((win & 31) << 3) + (t64 & 7);

    float v0 = x[((size_t)(b * 256 + c0)) * HW + y * IMW + xx];
    float v1 = x[((size_t)(b * 256 + c0 + 4)) * HW + y * IMW + xx];
    size_t wa = (size_t)b * 16777216 + (size_t)t8 * 2048 + (kt >> 1) * 128
                + 4 * (g * 4 + t4) + 2 * (kt & 1);
    float2 o = make_float2(tf32rf(v0), tf32rf(v1));
    *(float2*)(g_x + wa) = o;
}

// ---------------------------------------------------------------------------
// Tensor-core window attention, fragment-direct: one CTA (4 warps) per
// (window, head). K/V bulk cp.async (layout-preserving), Q LDG to regs,
// P via in-quad shuffles, O direct STG to packed g_attn.
// ---------------------------------------------------------------------------
__global__ __launch_bounds__(128) void attn_mma()
{
    extern __shared__ uint32_t smA[];   // K[4096] | V[4096] words
    const uint32_t smbase = smem_u32(smA);

    const int tid  = threadIdx.x;
    const int lane = tid & 31;
    const int wrp  = tid >> 5;
    const int g    = lane >> 2;
    const int t4   = lane & 3;

    const int win = blockIdx.x;
    const int hd  = blockIdx.y;
    const int b   = blockIdx.z;

    const size_t unit = ((size_t)(b * 4 + hd) * 1024 + win) * 4096;
    const float* gq = g_qkv + unit;
    const float* gk = g_qkv + KOFF + unit;
    const float* gv = g_qkv + VOFF + unit;

    // Stage K and V (layout-preserving bulk copy).
#pragma unroll
    for (int i = 0; i < 8; ++i) {
        int c = tid + i * 128;
        CP16(smbase + (uint32_t)c * 16u, gk + (size_t)c * 4);
        CP16(smbase + 16384u + (uint32_t)c * 16u, gv + (size_t)c * 4);
    }
    CP_COMMIT();

    // Q fragments for this warp's 16 rows (t-tile = wrp).
    uint4 qf[8];
#pragma unroll
    for (int kt = 0; kt < 8; ++kt)
        qf[kt] = *(const uint4*)(gq + wrp * 1024 + kt * 128 + lane * 4);

    CP_WAIT0();
    __syncthreads();

    const uint32_t* ksm = smA;
    const uint32_t* vsm = smA + 4096;

    // S = (0.125 q) k^T
    float acc[8][4];
#pragma unroll
    for (int nt = 0; nt < 8; ++nt)
#pragma unroll
        for (int r = 0; r < 4; ++r) acc[nt][r] = 0.f;

#pragma unroll
    for (int ks2 = 0; ks2 < 4; ++ks2)
#pragma unroll
        for (int nt = 0; nt < 8; ++nt) {
            uint4 kf = *(const uint4*)(ksm + (nt * 4 + ks2) * 128 + lane * 4);
            mma8(acc[nt], qf[2 * ks2].x, qf[2 * ks2].y, qf[2 * ks2].z, qf[2 * ks2].w,
                 kf.x, kf.y);
            mma8(acc[nt], qf[2 * ks2 + 1].x, qf[2 * ks2 + 1].y, qf[2 * ks2 + 1].z,
                 qf[2 * ks2 + 1].w, kf.z, kf.w);
        }

    // Softmax over rows r0, r0+8 (quad-distributed), deferred normalization.
    float mx0 = -1e30f, mx1 = -1e30f;
#pragma unroll
    for (int nt = 0; nt < 8; ++nt) {
        mx0 = fmaxf(mx0, fmaxf(acc[nt][0], acc[nt][1]));
        mx1 = fmaxf(mx1, fmaxf(acc[nt][2], acc[nt][3]));
    }
    mx0 = fmaxf(mx0, __shfl_xor_sync(0xffffffffu, mx0, 1));
    mx0 = fmaxf(mx0, __shfl_xor_sync(0xffffffffu, mx0, 2));
    mx1 = fmaxf(mx1, __shfl_xor_sync(0xffffffffu, mx1, 1));
    mx1 = fmaxf(mx1, __shfl_xor_sync(0xffffffffu, mx1, 2));

    float sm0 = 0.f, sm1 = 0.f;
#pragma unroll
    for (int nt = 0; nt < 8; ++nt) {
        acc[nt][0] = __expf(acc[nt][0] - mx0);
        acc[nt][1] = __expf(acc[nt][1] - mx0);
        acc[nt][2] = __expf(acc[nt][2] - mx1);
        acc[nt][3] = __expf(acc[nt][3] - mx1);
        sm0 += acc[nt][0] + acc[nt][1];
        sm1 += acc[nt][2] + acc[nt][3];
    }
    sm0 += __shfl_xor_sync(0xffffffffu, sm0, 1);
    sm0 += __shfl_xor_sync(0xffffffffu, sm0, 2);
    sm1 += __shfl_xor_sync(0xffffffffu, sm1, 1);
    sm1 += __shfl_xor_sync(0xffffffffu, sm1, 2);
    const float inv0 = 1.0f / sm0;
    const float inv1 = 1.0f / sm1;

    // O = P v: P A-fragments built from acc by in-quad shuffles.
    float oac[8][4];
#pragma unroll
    for (int nt = 0; nt < 8; ++nt)
#pragma unroll
        for (int r = 0; r < 4; ++r) oac[nt][r] = 0.f;

    const int s0 = 4 * g + (t4 >> 1);
    const int s1 = s0 + 2;
    const bool odd = (t4 & 1);

#pragma unroll
    for (int ut2 = 0; ut2 < 4; ++ut2) {
        uint32_t pa[2][4];
#pragma unroll
        for (int p = 0; p < 2; ++p) {
            const int ks = 2 * ut2 + p;
            float e0 = __shfl_sync(0xffffffffu, acc[ks][0], s0);
            float e1 = __shfl_sync(0xffffffffu, acc[ks][1], s0);
            float e2 = __shfl_sync(0xffffffffu, acc[ks][2], s0);
            float e3 = __shfl_sync(0xffffffffu, acc[ks][3], s0);
            float f0 = __shfl_sync(0xffffffffu, acc[ks][0], s1);
            float f1 = __shfl_sync(0xffffffffu, acc[ks][1], s1);
            float f2 = __shfl_sync(0xffffffffu, acc[ks][2], s1);
            float f3 = __shfl_sync(0xffffffffu, acc[ks][3], s1);
            pa[p][0] = tf32r(odd ? e1 : e0);
            pa[p][1] = tf32r(odd ? e3 : e2);
            pa[p][2] = tf32r(odd ? f1 : f0);
            pa[p][3] = tf32r(odd ? f3 : f2);
        }
#pragma unroll
        for (int nt = 0; nt < 8; ++nt) {
            uint4 vf = *(const uint4*)(vsm + (nt * 4 + ut2) * 128 + lane * 4);
            mma8(oac[nt], pa[0][0], pa[0][1], pa[0][2], pa[0][3], vf.x, vf.y);
            mma8(oac[nt], pa[1][0], pa[1][1], pa[1][2], pa[1][3], vf.z, vf.w);
        }
    }

    // Write O to pair-packed g_attn (tf32-rounded, normalized).
    float* ga = g_attn + (size_t)b * 16777216;
    const int t8base = win * 8 + 2 * wrp;
#pragma unroll
    for (int nt = 0; nt < 8; ++nt) {
        const int kt2 = hd * 4 + (nt >> 1);
#pragma unroll
        for (int rh = 0; rh < 2; ++rh) {
            const float inv = rh ? inv1 : inv0;
            float* gp = ga + (size_t)(t8base + rh) * 2048 + kt2 * 128;
#pragma unroll
            for (int e = 0; e < 2; ++e) {
                const int d23 = 2 * t4 + e;
                const int word = 4 * (g * 4 + (d23 & 3)) + 2 * (nt & 1) + (d23 >> 2);
                gp[word] = tf32rf(oac[nt][2 * rh + e] * inv);
            }
        }
    }
}

// ---------------------------------------------------------------------------
extern "C" void kernel_launch(void* const* d_in, const int* in_sizes, int n_in,
                              void* d_out, int out_size)
{
    (void)in_sizes; (void)n_in; (void)out_size;
    const float* x      = (const float*)d_in[0];
    const float* qkv_w  = (const float*)d_in[1];
    const float* qkv_b  = (const float*)d_in[2];
    const float* proj_w = (const float*)d_in[3];
    const float* proj_b = (const float*)d_in[4];
    float* out = (float*)d_out;

    static int attr_done = 0;
    if (!attr_done) {
        cudaFuncSetAttribute(qkv_mma,  cudaFuncAttributeMaxDynamicSharedMemorySize, SMEM_BYTES);
        cudaFuncSetAttribute(proj_mma, cudaFuncAttributeMaxDynamicSharedMemorySize, SMEM_BYTES);
        cudaFuncSetAttribute(attn_mma, cudaFuncAttributeMaxDynamicSharedMemorySize, ATTN_SMEM_BYTES);
        attr_done = 1;
    }

    cvt_weights<<<768, 256>>>(qkv_w, proj_w);
    cvt_x<<<262144, 256>>>(x);
    qkv_mma<<<dim3(6, 4096), 128, SMEM_BYTES>>>(qkv_b);
    attn_mma<<<dim3(1024, 4, 8), 128, ATTN_SMEM_BYTES>>>();
    proj_mma<<<dim3(2, 4096), 128, SMEM_BYTES>>>(proj_b, out);
}

// round 8
// speedup vs baseline: 6.3019x; 1.6519x over previous
#include <cuda_runtime.h>
#include <cuda_fp16.h>
#include <math.h>
#include <stdint.h>

// Problem constants: B=8, C=256, H=W=256, WS=8, HEADS=4, dh=64
#define HW  65536
#define IMW 256

// fp16 fragment-packed scratch (all m16n8k16 layouts), stored as u32 (half2):
//  h_qkv: Q | K | V regions, 2048 words per (b,hd,win) unit:
//   Q (A-frag): [tt 4][kc 4][lane*4 + hik*2 + him]
//   K (B-frag): [nt8 8][kc32 2][lane*4 + ks*2 + r]     (pairs over channel d)
//   V (B-frag): [dt8 8][uc32 2][lane*4 + ks*2 + r]     (pairs over token u)
//  h_x / h_attn (GEMM B): [b][t8 8192][s 8][lane*4 + ks*2 + r] (pairs over chan)
//  h_wq / h_wp (GEMM A): [mt][k16 16][lane*4 + hik*2 + him]
__device__ uint32_t h_qkv[201326592];
__device__ uint32_t h_x[67108864];
__device__ uint32_t h_attn[67108864];
__device__ uint32_t h_wq[98304];
__device__ uint32_t h_wp[32768];

#define KOFF 67108864
#define VOFF 134217728

__device__ __forceinline__ uint32_t smem_u32(const void* p) {
    uint32_t a;
    asm("{ .reg .u64 t; cvta.to.shared.u64 t, %1; cvt.u32.u64 %0, t; }" : "=r"(a) : "l"(p));
    return a;
}

__device__ __forceinline__ uint32_t h2(float lo, float hi) {
    __half2 h = __floats2half2_rn(lo, hi);
    return *(uint32_t*)&h;
}

__device__ __forceinline__ void mma16(float c[4],
                                      uint32_t a0, uint32_t a1, uint32_t a2, uint32_t a3,
                                      uint32_t b0, uint32_t b1) {
    asm volatile(
        "mma.sync.aligned.m16n8k16.row.col.f32.f16.f16.f32 "
        "{%0,%1,%2,%3}, {%4,%5,%6,%7}, {%8,%9}, {%0,%1,%2,%3};"
        : "+f"(c[0]), "+f"(c[1]), "+f"(c[2]), "+f"(c[3])
        : "r"(a0), "r"(a1), "r"(a2), "r"(a3), "r"(b0), "r"(b1));
}

#define CP16(dst, src) \
    asm volatile("cp.async.cg.shared.global [%0], [%1], 16;" :: "r"(dst), "l"(src) : "memory")
#define CP_COMMIT() asm volatile("cp.async.commit_group;" ::: "memory")
#define CP_WAIT1()  asm volatile("cp.async.wait_group 1;" ::: "memory")
#define CP_WAIT0()  asm volatile("cp.async.wait_group 0;" ::: "memory")

#define AWORDS 2048
#define BWORDS 2048
#define SMEM_BYTES (3 * (AWORDS + BWORDS) * 4)   // 49152
#define CVTX_SMEM (256 * 132 * 2)                // 67584

// ---------------------------------------------------------------------------
// Shared GEMM machinery: CTA 128x128, 4 warps of 64x64, K stepped by 32
// (2 x k16 MMA), 8 stages, 3-deep cp.async pipeline, fragment-packed fp16.
// ---------------------------------------------------------------------------
#define GEMM_ISSUE(S)                                                          \
    do {                                                                       \
        const int _s   = (S);                                                  \
        const int _buf = _s % 3;                                               \
        const uint32_t _aB = smbase + (uint32_t)(_buf * AWORDS) * 4u;          \
        const uint32_t _bB = smbase + (uint32_t)((3 * AWORDS + _buf * BWORDS)) * 4u; \
        _Pragma("unroll")                                                      \
        for (int _i = 0; _i < 4; ++_i) {                                       \
            int _c = tid + (_i << 7);                                          \
            CP16(_aB + (uint32_t)_c * 16u,                                     \
                 gA + ((size_t)(_c >> 6) * 2048 + _s * 256 + (_c & 63) * 4));  \
            CP16(_bB + (uint32_t)_c * 16u,                                     \
                 gB + ((size_t)(_c >> 5) * 1024 + _s * 128 + (_c & 31) * 4));  \
        }                                                                      \
        CP_COMMIT();                                                           \
    } while (0)

#define GEMM_COMPUTE(BUF)                                                      \
    do {                                                                       \
        const uint32_t* _A = dsm + (BUF) * AWORDS;                             \
        const uint32_t* _B = dsm + 3 * AWORDS + (BUF) * BWORDS;                \
        uint4 bf[8];                                                           \
        _Pragma("unroll")                                                      \
        for (int nt = 0; nt < 8; ++nt)                                         \
            bf[nt] = *(const uint4*)(_B + ((wn * 8 + nt) << 7) + (lane << 2)); \
        _Pragma("unroll")                                                      \
        for (int ks = 0; ks < 2; ++ks) {                                       \
            uint4 af[4];                                                       \
            _Pragma("unroll")                                                  \
            for (int mt = 0; mt < 4; ++mt)                                     \
                af[mt] = *(const uint4*)(_A + (((wm * 4 + mt) * 2 + ks) << 7)  \
                                              + (lane << 2));                  \
            _Pragma("unroll")                                                  \
            for (int mt = 0; mt < 4; ++mt)                                     \
                _Pragma("unroll")                                              \
                for (int nt = 0; nt < 8; ++nt)                                 \
                    mma16(acc[mt][nt], af[mt].x, af[mt].y, af[mt].z, af[mt].w, \
                          ks ? bf[nt].z : bf[nt].x, ks ? bf[nt].w : bf[nt].y); \
        }                                                                      \
    } while (0)

#define GEMM_PROLOG_AND_MAINLOOP()                                             \
    float acc[4][8][4];                                                        \
    _Pragma("unroll")                                                          \
    for (int mt = 0; mt < 4; ++mt)                                             \
        _Pragma("unroll")                                                      \
        for (int nt = 0; nt < 8; ++nt)                                         \
            _Pragma("unroll")                                                  \
            for (int r = 0; r < 4; ++r) acc[mt][nt][r] = 0.f;                  \
    GEMM_ISSUE(0);                                                             \
    GEMM_ISSUE(1);                                                             \
    _Pragma("unroll 1")                                                        \
    for (int s = 0; s < 8; ++s) {                                              \
        if (s < 7) { CP_WAIT1(); } else { CP_WAIT0(); }                        \
        __syncthreads();                                                       \
        if (s < 6) GEMM_ISSUE(s + 2);                                          \
        GEMM_COMPUTE(s % 3);                                                   \
    }

// ---------------------------------------------------------------------------
// GEMM 1: qkv = qkv_w @ x + qkv_b; epilogue packs fp16 Q/K/V fragments.
// ---------------------------------------------------------------------------
__global__ __launch_bounds__(128) void qkv_mma(const float* __restrict__ bias)
{
    extern __shared__ uint32_t dsm[];
    const uint32_t smbase = smem_u32(dsm);

    const int tid  = threadIdx.x;
    const int lane = tid & 31;
    const int wid  = tid >> 5;
    const int g    = lane >> 2;
    const int t4   = lane & 3;
    const int wm   = wid >> 1;
    const int wn   = wid & 1;

    const int gy = blockIdx.y;
    const int b  = gy >> 9;
    const int tl = gy & 511;
    const int w0 = tl << 1;

    const uint32_t* gA = h_wq + (size_t)blockIdx.x * 8 * 2048;
    const uint32_t* gB = h_x + (size_t)b * 8388608 + (size_t)tl * 16384;

    GEMM_PROLOG_AND_MAINLOOP();

    const int g64  = 2 * blockIdx.x + wm;
    const int head = g64 / 3;
    const int typ  = g64 % 3;
    const size_t ubase = (size_t)((b * 4 + head) * 1024 + w0 + wn) * 2048;
    const int e  = g & 1;
    const int pj = g >> 1;

    if (typ == 0) {
        uint32_t* gout = h_qkv + ubase;
#pragma unroll
        for (int mt = 0; mt < 4; ++mt)
#pragma unroll
            for (int half = 0; half < 2; ++half) {
                const float bv = bias[g64 * 64 + mt * 16 + 8 * half + g];
#pragma unroll
                for (int nt = 0; nt < 8; ++nt) {
                    float v0 = 0.125f * (acc[mt][nt][2 * half + 0] + bv);
                    float v1 = 0.125f * (acc[mt][nt][2 * half + 1] + bv);
                    float p0 = __shfl_xor_sync(0xffffffffu, v0, 4);
                    float p1 = __shfl_xor_sync(0xffffffffu, v1, 4);
                    float lo = e ? p1 : v0;
                    float hi = e ? v1 : p0;
                    int word = (nt >> 1) * 512 + mt * 128
                               + ((2 * t4 + e) * 4 + pj) * 4 + half * 2 + (nt & 1);
                    gout[word] = h2(lo, hi);
                }
            }
    } else if (typ == 1) {
        uint32_t* gout = h_qkv + KOFF + ubase;
#pragma unroll
        for (int mt = 0; mt < 4; ++mt)
#pragma unroll
            for (int half = 0; half < 2; ++half) {
                const float bv = bias[g64 * 64 + mt * 16 + 8 * half + g];
#pragma unroll
                for (int nt = 0; nt < 8; ++nt) {
                    float v0 = acc[mt][nt][2 * half + 0] + bv;
                    float v1 = acc[mt][nt][2 * half + 1] + bv;
                    float p0 = __shfl_xor_sync(0xffffffffu, v0, 4);
                    float p1 = __shfl_xor_sync(0xffffffffu, v1, 4);
                    float lo = e ? p1 : v0;
                    float hi = e ? v1 : p0;
                    int word = (nt * 2 + (mt >> 1)) * 128
                               + ((2 * t4 + e) * 4 + pj) * 4 + (mt & 1) * 2 + half;
                    gout[word] = h2(lo, hi);
                }
            }
    } else {
        uint32_t* gout = h_qkv + VOFF + ubase;
#pragma unroll
        for (int mt = 0; mt < 4; ++mt)
#pragma unroll
            for (int half = 0; half < 2; ++half) {
                const float bv = bias[g64 * 64 + mt * 16 + 8 * half + g];
#pragma unroll
                for (int nt = 0; nt < 8; ++nt) {
                    float v0 = acc[mt][nt][2 * half + 0] + bv;
                    float v1 = acc[mt][nt][2 * half + 1] + bv;
                    int word = ((mt * 2 + half) * 2 + (nt >> 2)) * 128
                               + (g * 4 + t4) * 4 + ((nt >> 1) & 1) * 2 + (nt & 1);
                    gout[word] = h2(v0, v1);
                }
            }
    }
}

// ---------------------------------------------------------------------------
// GEMM 2: out = proj_w @ attn + proj_b  (fp32 raster scatter epilogue)
// ---------------------------------------------------------------------------
__global__ __launch_bounds__(128) void proj_mma(const float* __restrict__ bias,
                                                float* __restrict__ out)
{
    extern __shared__ uint32_t dsm[];
    const uint32_t smbase = smem_u32(dsm);

    const int tid  = threadIdx.x;
    const int lane = tid & 31;
    const int wid  = tid >> 5;
    const int g    = lane >> 2;
    const int t4   = lane & 3;
    const int wm   = wid >> 1;
    const int wn   = wid & 1;

    const int m0 = blockIdx.x << 7;
    const int gy = blockIdx.y;
    const int b  = gy >> 9;
    const int tl = gy & 511;
    const int w0 = tl << 1;

    const uint32_t* gA = h_wp + (size_t)blockIdx.x * 8 * 2048;
    const uint32_t* gB = h_attn + (size_t)b * 8388608 + (size_t)tl * 16384;

    GEMM_PROLOG_AND_MAINLOOP();

#pragma unroll
    for (int mt = 0; mt < 4; ++mt) {
#pragma unroll
        for (int half = 0; half < 2; ++half) {
            const int o = m0 + wm * 64 + mt * 16 + g + half * 8;
            const float bv = bias[o];
            float* obase = out + ((size_t)b * 256 + o) * HW;
#pragma unroll
            for (int nt = 0; nt < 8; ++nt) {
                const int col = wn * 64 + nt * 8 + 2 * t4;
                const int win = w0 + (col >> 6);
                const int t64 = col & 63;
                const int y   = ((win >> 5) << 3) + (t64 >> 3);
                const int xx  = ((win & 31) << 3) + (t64 & 7);
                float2 ov = make_float2(acc[mt][nt][2 * half] + bv,
                                        acc[mt][nt][2 * half + 1] + bv);
                *(float2*)(obase + y * IMW + xx) = ov;
            }
        }
    }
}

// ---------------------------------------------------------------------------
// Prepass: fp16-round weights into A-fragment-packed layout.
// ---------------------------------------------------------------------------
__global__ __launch_bounds__(256) void cvt_weights(const float* __restrict__ qw,
                                                   const float* __restrict__ pw)
{
    int i = blockIdx.x * 256 + threadIdx.x;
    if (i < 196608) {
        int o = i >> 8, c = i & 255;
        int word = (o >> 4) * 2048 + (c >> 4) * 128
                   + ((o & 7) * 4 + (((c & 15) & 7) >> 1)) * 4
                   + ((c >> 3) & 1) * 2 + ((o >> 3) & 1);
        ((__half*)h_wq)[word * 2 + (c & 1)] = __float2half_rn(qw[i]);
    }
    if (i < 65536) {
        int o = i >> 8, c = i & 255;
        int word = (o >> 4) * 2048 + (c >> 4) * 128
                   + ((o & 7) * 4 + (((c & 15) & 7) >> 1)) * 4
                   + ((c >> 3) & 1) * 2 + ((o >> 3) & 1);
        ((__half*)h_wp)[word * 2 + (c & 1)] = __float2half_rn(pw[i]);
    }
}

// ---------------------------------------------------------------------------
// Prepass: fp16 + window-major + B-fragment-pack x via smem transpose.
// One CTA per (b, 128-token tile); coalesced LDG and STG.
// ---------------------------------------------------------------------------
__global__ __launch_bounds__(256) void cvt_x(const float* __restrict__ x)
{
    extern __shared__ __half sh[];   // [256][132]
    const int bt = blockIdx.x;
    const int b  = bt >> 9, tl = bt & 511;
    const int tid = threadIdx.x;
    const int w0 = tl << 1;

#pragma unroll 4
    for (int it = 0; it < 32; ++it) {
        int idx = it * 256 + tid;
        int c = idx >> 5, tq = idx & 31;
        int tok4 = tq << 2;
        int win = w0 + (tok4 >> 6), t64 = tok4 & 63;
        int y = ((win >> 5) << 3) + (t64 >> 3), xx = ((win & 31) << 3) + (t64 & 7);
        float4 v = *(const float4*)(x + ((size_t)(b * 256 + c)) * HW + y * IMW + xx);
        __half2* dst = (__half2*)(sh + c * 132 + tok4);
        dst[0] = __floats2half2_rn(v.x, v.y);
        dst[1] = __floats2half2_rn(v.z, v.w);
    }
    __syncthreads();

    uint32_t* outp = h_x + (size_t)b * 8388608 + (size_t)tl * 16384;
#pragma unroll 4
    for (int it = 0; it < 64; ++it) {
        int widx = it * 256 + tid;
        int t8L = widx >> 10, rest = widx & 1023;
        int s = rest >> 7, lw = rest & 127;
        int lc = lw >> 2, sub = lw & 3;
        int ks = sub >> 1, r = sub & 1;
        int gg = lc >> 2, tt4 = lc & 3;
        int tok = t8L * 8 + gg;
        int c0 = s * 32 + ks * 16 + r * 8 + 2 * tt4;
        outp[widx] = h2(__half2float(sh[c0 * 132 + tok]),
                        __half2float(sh[(c0 + 1) * 132 + tok]));
    }
}

// ---------------------------------------------------------------------------
// fp16 tensor-core window attention: one CTA (4 warps) per (window, head).
// K/V bulk cp.async, Q LDG, P fragments = pure register repack (no shuffles).
// ---------------------------------------------------------------------------
__global__ __launch_bounds__(128) void attn_mma()
{
    __shared__ uint32_t sm[4096];    // K[2048] | V[2048]
    const uint32_t smbase = smem_u32(sm);

    const int tid  = threadIdx.x;
    const int lane = tid & 31;
    const int wrp  = tid >> 5;
    const int g    = lane >> 2;
    const int t4   = lane & 3;

    const int win = blockIdx.x;
    const int hd  = blockIdx.y;
    const int b   = blockIdx.z;

    const size_t unit = (size_t)((b * 4 + hd) * 1024 + win) * 2048;
    const uint32_t* gq = h_qkv + unit;
    const uint32_t* gk = h_qkv + KOFF + unit;
    const uint32_t* gv = h_qkv + VOFF + unit;

#pragma unroll
    for (int i = 0; i < 4; ++i) {
        int c = tid + i * 128;
        CP16(smbase + (uint32_t)c * 16u, gk + (size_t)c * 4);
        CP16(smbase + 8192u + (uint32_t)c * 16u, gv + (size_t)c * 4);
    }
    CP_COMMIT();

    uint4 qf[4];
#pragma unroll
    for (int kc = 0; kc < 4; ++kc)
        qf[kc] = *(const uint4*)(gq + wrp * 512 + kc * 128 + lane * 4);

    CP_WAIT0();
    __syncthreads();

    const uint32_t* ksm = sm;
    const uint32_t* vsm = sm + 2048;

    // S = (0.125 q) k^T
    float acc[8][4];
#pragma unroll
    for (int nt = 0; nt < 8; ++nt)
#pragma unroll
        for (int r = 0; r < 4; ++r) acc[nt][r] = 0.f;

#pragma unroll
    for (int c32 = 0; c32 < 2; ++c32)
#pragma unroll
        for (int nt = 0; nt < 8; ++nt) {
            uint4 kf = *(const uint4*)(ksm + (nt * 2 + c32) * 128 + lane * 4);
            mma16(acc[nt], qf[2 * c32].x, qf[2 * c32].y, qf[2 * c32].z, qf[2 * c32].w,
                  kf.x, kf.y);
            mma16(acc[nt], qf[2 * c32 + 1].x, qf[2 * c32 + 1].y, qf[2 * c32 + 1].z,
                  qf[2 * c32 + 1].w, kf.z, kf.w);
        }

    // Softmax over rows g, g+8 (quad-distributed), deferred normalization.
    float mx0 = -1e30f, mx1 = -1e30f;
#pragma unroll
    for (int nt = 0; nt < 8; ++nt) {
        mx0 = fmaxf(mx0, fmaxf(acc[nt][0], acc[nt][1]));
        mx1 = fmaxf(mx1, fmaxf(acc[nt][2], acc[nt][3]));
    }
    mx0 = fmaxf(mx0, __shfl_xor_sync(0xffffffffu, mx0, 1));
    mx0 = fmaxf(mx0, __shfl_xor_sync(0xffffffffu, mx0, 2));
    mx1 = fmaxf(mx1, __shfl_xor_sync(0xffffffffu, mx1, 1));
    mx1 = fmaxf(mx1, __shfl_xor_sync(0xffffffffu, mx1, 2));

    float sm0 = 0.f, sm1 = 0.f;
#pragma unroll
    for (int nt = 0; nt < 8; ++nt) {
        acc[nt][0] = __expf(acc[nt][0] - mx0);
        acc[nt][1] = __expf(acc[nt][1] - mx0);
        acc[nt][2] = __expf(acc[nt][2] - mx1);
        acc[nt][3] = __expf(acc[nt][3] - mx1);
        sm0 += acc[nt][0] + acc[nt][1];
        sm1 += acc[nt][2] + acc[nt][3];
    }
    sm0 += __shfl_xor_sync(0xffffffffu, sm0, 1);
    sm0 += __shfl_xor_sync(0xffffffffu, sm0, 2);
    sm1 += __shfl_xor_sync(0xffffffffu, sm1, 1);
    sm1 += __shfl_xor_sync(0xffffffffu, sm1, 2);
    const float inv0 = 1.0f / sm0;
    const float inv1 = 1.0f / sm1;

    // P A-fragments: direct repack of the S accumulator (fp16 layout magic).
    uint32_t pa[4][4];
#pragma unroll
    for (int u = 0; u < 4; ++u) {
        pa[u][0] = h2(acc[2 * u][0],     acc[2 * u][1]);
        pa[u][1] = h2(acc[2 * u][2],     acc[2 * u][3]);
        pa[u][2] = h2(acc[2 * u + 1][0], acc[2 * u + 1][1]);
        pa[u][3] = h2(acc[2 * u + 1][2], acc[2 * u + 1][3]);
    }

    // O = P v
    float oac[8][4];
#pragma unroll
    for (int nt = 0; nt < 8; ++nt)
#pragma unroll
        for (int r = 0; r < 4; ++r) oac[nt][r] = 0.f;

#pragma unroll
    for (int uc32 = 0; uc32 < 2; ++uc32)
#pragma unroll
        for (int nt = 0; nt < 8; ++nt) {
            uint4 vf = *(const uint4*)(vsm + (nt * 2 + uc32) * 128 + lane * 4);
            mma16(oac[nt], pa[2 * uc32][0], pa[2 * uc32][1], pa[2 * uc32][2],
                  pa[2 * uc32][3], vf.x, vf.y);
            mma16(oac[nt], pa[2 * uc32 + 1][0], pa[2 * uc32 + 1][1],
                  pa[2 * uc32 + 1][2], pa[2 * uc32 + 1][3], vf.z, vf.w);
        }

    // Pack O into h_attn B-fragment layout (pairs over channel = in-thread).
    uint32_t* ga = h_attn + (size_t)b * 8388608;
    const int t8b = win * 8 + wrp * 2;
#pragma unroll
    for (int nt = 0; nt < 8; ++nt) {
        const int s  = hd * 2 + (nt >> 2);
        const int ks = (nt >> 1) & 1;
        const int r  = nt & 1;
#pragma unroll
        for (int rh = 0; rh < 2; ++rh) {
            const float inv = rh ? inv1 : inv0;
            int word = (t8b + rh) * 1024 + s * 128 + (g * 4 + t4) * 4 + ks * 2 + r;
            ga[word] = h2(oac[nt][2 * rh] * inv, oac[nt][2 * rh + 1] * inv);
        }
    }
}

// ---------------------------------------------------------------------------
extern "C" void kernel_launch(void* const* d_in, const int* in_sizes, int n_in,
                              void* d_out, int out_size)
{
    (void)in_sizes; (void)n_in; (void)out_size;
    const float* x      = (const float*)d_in[0];
    const float* qkv_w  = (const float*)d_in[1];
    const float* qkv_b  = (const float*)d_in[2];
    const float* proj_w = (const float*)d_in[3];
    const float* proj_b = (const float*)d_in[4];
    float* out = (float*)d_out;

    static int attr_done = 0;
    if (!attr_done) {
        cudaFuncSetAttribute(qkv_mma,  cudaFuncAttributeMaxDynamicSharedMemorySize, SMEM_BYTES);
        cudaFuncSetAttribute(proj_mma, cudaFuncAttributeMaxDynamicSharedMemorySize, SMEM_BYTES);
        cudaFuncSetAttribute(cvt_x,    cudaFuncAttributeMaxDynamicSharedMemorySize, CVTX_SMEM);
        attr_done = 1;
    }

    cvt_weights<<<768, 256>>>(qkv_w, proj_w);
    cvt_x<<<4096, 256, CVTX_SMEM>>>(x);
    qkv_mma<<<dim3(6, 4096), 128, SMEM_BYTES>>>(qkv_b);
    attn_mma<<<dim3(1024, 4, 8), 128>>>();
    proj_mma<<<dim3(2, 4096), 128, SMEM_BYTES>>>(proj_b, out);
}